// round 13
// baseline (speedup 1.0000x reference)
#include <cuda_runtime.h>
#include <cuda_bf16.h>
#include <cstdint>

#define NAGENTS 32768
#define HDIM    256
#define ODIM    64
#define NGROUPS 1024
#define GSIZE   32
#define TSTEPS  (NAGENTS + 1)
#define ZROWS   1026   /* 1024 pooled + goal + zero-feat row */

// ---------------- device scratch (allocation-free) ----------------
__device__ float g_X[NAGENTS * HDIM];
__device__ float g_Y[NAGENTS * HDIM];
__device__ float g_R[ZROWS * HDIM];          // rows: pooled[0..1023], goal_emb, zeros
__device__ float g_zs[ZROWS * 1024];         // distinct input projections (+bias)
__device__ float g_hs[TSTEPS * HDIM];        // all hidden states
__device__ int   g_rowidx[NAGENTS];

// ---------------- PTX helpers ----------------
__device__ __forceinline__ uint32_t smem_u32(const void* p) {
    return (uint32_t)__cvta_generic_to_shared(p);
}
__device__ __forceinline__ uint32_t mapa_u32(uint32_t addr, uint32_t rank) {
    uint32_t r;
    asm("mapa.shared::cluster.u32 %0, %1, %2;" : "=r"(r) : "r"(addr), "r"(rank));
    return r;
}
// one 64B bulk DSMEM copy = ONE complete_tx update at the dest barrier
__device__ __forceinline__ void bulk_s2s(uint32_t daddr, uint32_t saddr,
                                         uint32_t bytes, uint32_t dbar) {
    asm volatile("cp.async.bulk.shared::cluster.shared::cta.mbarrier::complete_tx::bytes "
                 "[%0], [%1], %2, [%3];"
                 :: "r"(daddr), "r"(saddr), "r"(bytes), "r"(dbar) : "memory");
}
__device__ __forceinline__ void fence_proxy_async_cta() {
    asm volatile("fence.proxy.async.shared::cta;" ::: "memory");
}
__device__ __forceinline__ void mbar_init(uint32_t addr, uint32_t cnt) {
    asm volatile("mbarrier.init.shared.b64 [%0], %1;" :: "r"(addr), "r"(cnt) : "memory");
}
__device__ __forceinline__ void mbar_arrive_expect_tx(uint32_t addr, uint32_t bytes) {
    asm volatile("mbarrier.arrive.expect_tx.shared.b64 _, [%0], %1;"
                 :: "r"(addr), "r"(bytes) : "memory");
}
// CTA-scope acquire wait: async txs commit remote data to OUR smem before
// complete_tx is counted; acquire.cta orders our subsequent ld.shared.
__device__ __forceinline__ void mbar_wait(uint32_t addr, uint32_t parity) {
    asm volatile(
        "{\n\t.reg .pred P;\n\t"
        "WL_%=:\n\t"
        "mbarrier.try_wait.parity.acquire.cta.shared::cta.b64 P, [%0], %1, 0x989680;\n\t"
        "@P bra.uni WD_%=;\n\t"
        "bra.uni WL_%=;\n\t"
        "WD_%=:\n\t}"
        :: "r"(addr), "r"(parity) : "memory");
}
__device__ __forceinline__ uint32_t ctarank() {
    uint32_t r; asm("mov.u32 %0, %%cluster_ctarank;" : "=r"(r)); return r;
}
// Fast gates via single-op MUFU.TANH (tanh.approx.f32, sm_75+).
// sigmoid(x) = 0.5*tanh(x/2) + 0.5.
__device__ __forceinline__ float ftanh_fast(float x) {
    float y;
    asm("tanh.approx.f32 %0, %1;" : "=f"(y) : "f"(x));
    return y;
}
__device__ __forceinline__ float fsig_fast(float x) {
    float y;
    asm("tanh.approx.f32 %0, %1;" : "=f"(y) : "f"(x * 0.5f));
    return fmaf(0.5f, y, 0.5f);
}
// packed f32x2 FMA (SASS FFMA2 — only reachable via PTX)
#define FFMA2(acc, a, b) \
    asm("fma.rn.f32x2 %0, %1, %2, %3;" : "=l"(acc) : "l"(a), "l"(b), "l"(acc))
__device__ __forceinline__ unsigned long long pack_f32x2(float lo, float hi) {
    unsigned long long r;
    asm("mov.b64 %0, {%1, %2};" : "=l"(r) : "r"(__float_as_uint(lo)), "r"(__float_as_uint(hi)));
    return r;
}
__device__ __forceinline__ float2 unpack_f32x2(unsigned long long v) {
    uint32_t lo, hi;
    asm("mov.b64 {%0, %1}, %2;" : "=r"(lo), "=r"(hi) : "l"(v));
    return make_float2(__uint_as_float(lo), __uint_as_float(hi));
}

// ---------------- goal embedding ----------------
__global__ void k_goal(const float* __restrict__ goal, const float* __restrict__ W,
                       const float* __restrict__ b, float* __restrict__ R) {
    __shared__ float gs[HDIM];
    int j = threadIdx.x;
    gs[j] = goal[j];
    __syncthreads();
    float acc = 0.f;
    #pragma unroll 8
    for (int k = 0; k < HDIM; k++) acc = fmaf(gs[k], W[k * HDIM + j], acc);
    R[1024 * HDIM + j] = fmaxf(acc + b[j], 0.f);
    R[1025 * HDIM + j] = 0.f;
}

// ---------------- rowidx ----------------
__global__ void k_rowidx_init(int* __restrict__ ri) {
    int i = blockIdx.x * blockDim.x + threadIdx.x;
    if (i < NAGENTS) ri[i] = 1025;
}
__global__ void k_rowidx_scatter(const int* __restrict__ groups, int* __restrict__ ri) {
    int e = blockIdx.x * blockDim.x + threadIdx.x;
    if (e < NGROUPS * GSIZE) ri[groups[e]] = e >> 5;
}

// ---------------- group aggregate ----------------
template <int GATHER>
__global__ void k_group(const float* __restrict__ src, const int* __restrict__ groups,
                        float* __restrict__ U) {
    __shared__ float rows[GSIZE][HDIM];
    __shared__ int   idx[GSIZE];
    int g = blockIdx.x, t = threadIdx.x;
    if (GATHER) {
        if (t < GSIZE) idx[t] = groups[g * GSIZE + t];
        __syncthreads();
    }
    #pragma unroll 4
    for (int m = 0; m < GSIZE; m++) {
        int r = GATHER ? idx[m] : (g * GSIZE + m);
        rows[m][t] = src[r * HDIM + t];
    }
    __syncthreads();
    float s = 0.f;
    #pragma unroll
    for (int m = 0; m < GSIZE; m++) s += rows[m][t];
    const float inv = 1.0f / 33.0f;
    #pragma unroll 4
    for (int m = 0; m < GSIZE; m++)
        U[(g * GSIZE + m) * HDIM + t] = (rows[m][t] + s) * inv;
}

// ---------------- pool ----------------
__global__ void k_pool(const float* __restrict__ H2, float* __restrict__ R) {
    int g = blockIdx.x, t = threadIdx.x;
    float s = 0.f;
    #pragma unroll
    for (int m = 0; m < GSIZE; m++) s += H2[(g * GSIZE + m) * HDIM + t];
    R[g * HDIM + t] = s * (1.0f / 32.0f);
}

// ---------------- tiled SGEMM: C = act(A[M,K]@B[K,N] + bias) ----------------
__global__ __launch_bounds__(256) void k_gemm(
    const float* __restrict__ A, const float* __restrict__ B,
    const float* __restrict__ bias, float* __restrict__ C,
    int M, int N, int K, int doRelu)
{
    __shared__ float As[64][20];
    __shared__ float Bs[16][64];
    int t = threadIdx.x;
    int tx = t & 15, ty = t >> 4;
    int bm = blockIdx.y * 64, bn = blockIdx.x * 64;
    int row0 = ty * 4, col0 = tx * 4;
    float acc[4][4];
    #pragma unroll
    for (int i = 0; i < 4; i++)
        #pragma unroll
        for (int j = 0; j < 4; j++) acc[i][j] = 0.f;

    int am = t >> 2, ak4 = (t & 3) * 4;
    for (int kb = 0; kb < K; kb += 16) {
        float4 av = make_float4(0.f, 0.f, 0.f, 0.f);
        if (bm + am < M)
            av = *reinterpret_cast<const float4*>(&A[(size_t)(bm + am) * K + kb + ak4]);
        *reinterpret_cast<float4*>(&As[am][ak4]) = av;
        #pragma unroll
        for (int i = 0; i < 4; i++) {
            int e = t + i * 256;
            int k = e >> 6, n = e & 63;
            Bs[k][n] = B[(size_t)(kb + k) * N + bn + n];
        }
        __syncthreads();
        #pragma unroll
        for (int k = 0; k < 16; k++) {
            float a0 = As[row0 + 0][k], a1 = As[row0 + 1][k];
            float a2 = As[row0 + 2][k], a3 = As[row0 + 3][k];
            float4 bv = *reinterpret_cast<const float4*>(&Bs[k][col0]);
            acc[0][0] = fmaf(a0, bv.x, acc[0][0]); acc[0][1] = fmaf(a0, bv.y, acc[0][1]);
            acc[0][2] = fmaf(a0, bv.z, acc[0][2]); acc[0][3] = fmaf(a0, bv.w, acc[0][3]);
            acc[1][0] = fmaf(a1, bv.x, acc[1][0]); acc[1][1] = fmaf(a1, bv.y, acc[1][1]);
            acc[1][2] = fmaf(a1, bv.z, acc[1][2]); acc[1][3] = fmaf(a1, bv.w, acc[1][3]);
            acc[2][0] = fmaf(a2, bv.x, acc[2][0]); acc[2][1] = fmaf(a2, bv.y, acc[2][1]);
            acc[2][2] = fmaf(a2, bv.z, acc[2][2]); acc[2][3] = fmaf(a2, bv.w, acc[2][3]);
            acc[3][0] = fmaf(a3, bv.x, acc[3][0]); acc[3][1] = fmaf(a3, bv.y, acc[3][1]);
            acc[3][2] = fmaf(a3, bv.z, acc[3][2]); acc[3][3] = fmaf(a3, bv.w, acc[3][3]);
        }
        __syncthreads();
    }
    #pragma unroll
    for (int i = 0; i < 4; i++) {
        int r = bm + row0 + i;
        if (r >= M) break;
        #pragma unroll
        for (int j = 0; j < 4; j++) {
            float v = acc[i][j] + bias[bn + col0 + j];
            if (doRelu) v = fmaxf(v, 0.f);
            C[(size_t)r * N + bn + col0 + j] = v;
        }
    }
}

// ---------------- persistent 16-CTA-cluster LSTM (bulk-copy fan-out) ----------------
// CTA r owns hidden indices [r*16, r*16+16) and gate cols {g*256 + r*16 + j}.
// 512 threads: warp w lane l -> local col lc = w*4+(l&3) (64 cols), k-slice l>>2 (8x32k).
// Exchange: warp 0 stages 16 h floats (64B, double-buffered), lanes 0-15 each issue
// ONE cp.async.bulk 64B copy to one dest CTA -> dest barrier sees 16 txs/step
// (vs 256 with per-lane st.async -> removes barrier tx-accumulation serialization).
#define HPAD    36
#define HBUFW   (8 * HPAD)          /* 288 words */
#define HBYTES  (HBUFW * 4)         /* 1152 B    */
#define BAROFF  (2 * HBYTES)        /* 2304      */
#define PAOFF   (BAROFF + 16)       /* 2320      */
#define STGOFF  (PAOFF + 2 * 64 * 4)/* 2832      */
#define SMBYTES (STGOFF + 2 * 64)

__global__ __launch_bounds__(512, 1)
void k_lstm(const float* __restrict__ zs, const int* __restrict__ rowidx,
            const float* __restrict__ W_hh, float* __restrict__ hs)
{
    __shared__ __align__(16) unsigned char sm[SMBYTES];
    float* smf = reinterpret_cast<float*>(sm);

    const int t = threadIdx.x;
    const int l = t & 31;
    const int w = t >> 5;
    const int lc   = w * 4 + (l & 3);   // local gate-col 0..63
    const int ksl  = l >> 2;            // k-slice 0..7 (32 k each)
    const int gate = lc >> 4;
    const int j    = lc & 15;
    const uint32_t rank = ctarank();
    const int base = rank * 16;
    const int gcol = gate * 256 + base + j;

    // resident packed W_hh slice: 16 f32x2 regs (32 k-values for this col)
    unsigned long long w2[16];
    #pragma unroll
    for (int q = 0; q < 16; q++)
        w2[q] = pack_f32x2(W_hh[(size_t)(ksl * 32 + 2 * q) * 1024 + gcol],
                           W_hh[(size_t)(ksl * 32 + 2 * q + 1) * 1024 + gcol]);

    // zero both h buffers (incl. padding)
    for (int i = t; i < 2 * HBUFW; i += 512) smf[i] = 0.f;

    const uint32_t smb = smem_u32(sm);
    if (t == 0) {
        mbar_init(smb + BAROFF, 1);
        mbar_init(smb + BAROFF + 8, 1);
        mbar_arrive_expect_tx(smb + BAROFF, 1024);      // 16 CTAs x 64 B
        mbar_arrive_expect_tx(smb + BAROFF + 8, 1024);
        asm volatile("fence.mbarrier_init.release.cluster;" ::: "memory");
    }
    __syncthreads();
    asm volatile("barrier.cluster.arrive.aligned;" ::: "memory");
    asm volatile("barrier.cluster.wait.aligned;" ::: "memory");

    // warp 0 lane l (<16): remote smem base of dest rank l
    uint32_t rdst = 0;
    if (w == 0 && l < 16) rdst = mapa_u32(smb, (uint32_t)l);
    // byte offset of OUR 16-float block inside any h buffer (16B aligned:
    // 144*(rank>>1) + 64*(rank&1))
    const uint32_t myblk = 4u * ((rank >> 1) * HPAD + (rank & 1) * 16);

    float c = 0.f;                 // cell state for col l (warp 0 lanes 0..15)
    uint32_t ph0 = 0, ph1 = 0;

    for (int step = 0; step < TSTEPS; step++) {
        // warp 0 lanes 0..15: prefetch z gate values (hidden under the wait's poll)
        float z0 = 0.f, z1 = 0.f, z2 = 0.f, z3 = 0.f;
        if (t < 16) {
            int row = (step == NAGENTS) ? 1024 : __ldg(&rowidx[step]);
            const float* zr = zs + (size_t)row * 1024 + base + t;
            z0 = __ldg(zr);
            z1 = __ldg(zr + 256);
            z2 = __ldg(zr + 512);
            z3 = __ldg(zr + 768);
        }

        const int buf = step & 1;
        if (step > 0) {            // wait for h(step-1) fan-in (CTA-scope acquire)
            if (buf) { mbar_wait(smb + BAROFF + 8, ph1); ph1 ^= 1; }
            else     { mbar_wait(smb + BAROFF, ph0); ph0 ^= 1; }
            if (t == 0) mbar_arrive_expect_tx(smb + BAROFF + (buf ? 8 : 0), 1024);
        }

        // matvec: 32 k for (col, slice); padded slices (144B apart) -> conflict-free LDS.128
        const ulonglong2* hp = reinterpret_cast<const ulonglong2*>(
            sm + buf * HBYTES + ksl * (HPAD * 4));
        unsigned long long a0 = 0ull, a1 = 0ull;
        #pragma unroll
        for (int q = 0; q < 4; q++) {
            ulonglong2 ha = hp[2 * q];
            ulonglong2 hb = hp[2 * q + 1];
            FFMA2(a0, ha.x, w2[4 * q + 0]);
            FFMA2(a1, ha.y, w2[4 * q + 1]);
            FFMA2(a0, hb.x, w2[4 * q + 2]);
            FFMA2(a1, hb.y, w2[4 * q + 3]);
        }
        float2 f0 = unpack_f32x2(a0), f1 = unpack_f32x2(a1);
        float v = (f0.x + f0.y) + (f1.x + f1.y);
        // reduce across the 8 k-slices (lane bits 2,3,4)
        v += __shfl_xor_sync(0xffffffffu, v, 4);
        v += __shfl_xor_sync(0xffffffffu, v, 8);
        v += __shfl_xor_sync(0xffffffffu, v, 16);
        if (l < 4) smf[(PAOFF >> 2) + buf * 64 + j * 4 + gate] = v;  // pa[buf][j][gate]
        __syncthreads();                                              // one bar per step

        // warp 0 only: gates + stage + bulk fan-out
        if (w == 0) {
            const uint32_t nb = (uint32_t)((step + 1) & 1);
            if (l < 16) {
                float4 g4 = *reinterpret_cast<const float4*>(
                    &smf[(PAOFF >> 2) + buf * 64 + l * 4]);
                float zi = g4.x + z0, zf = g4.y + z1, zg = g4.z + z2, zo = g4.w + z3;
                c = fsig_fast(zf) * c + fsig_fast(zi) * ftanh_fast(zg);
                float h = fsig_fast(zo) * ftanh_fast(c);
                smf[(STGOFF >> 2) + nb * 16 + l] = h;   // stage (double-buffered)
                hs[step * HDIM + base + l] = h;
            }
            __syncwarp();
            fence_proxy_async_cta();   // order staging STS before async-proxy read
            if (l < 16 && step + 1 < TSTEPS) {
                bulk_s2s(rdst + nb * HBYTES + myblk,
                         smb + STGOFF + nb * 64, 64,
                         rdst + BAROFF + nb * 8u);
            }
        }
    }
}

// ---------------- output: softmax(hs@W_act + b_act) ----------------
__global__ __launch_bounds__(256) void k_out(const float* __restrict__ hs,
                                             const float* __restrict__ W,
                                             const float* __restrict__ b,
                                             float* __restrict__ out) {
    __shared__ float hrow[8][HDIM];
    int warp = threadIdx.x >> 5, lane = threadIdx.x & 31;
    int row = blockIdx.x * 8 + warp;
    if (row >= TSTEPS) return;
    #pragma unroll
    for (int q = 0; q < 8; q++)
        hrow[warp][lane + q * 32] = hs[row * HDIM + lane + q * 32];
    __syncwarp();
    int c0 = lane, c1 = lane + 32;
    float acc0 = b[c0], acc1 = b[c1];
    #pragma unroll 8
    for (int k = 0; k < HDIM; k++) {
        float h = hrow[warp][k];
        acc0 = fmaf(h, __ldg(&W[k * ODIM + c0]), acc0);
        acc1 = fmaf(h, __ldg(&W[k * ODIM + c1]), acc1);
    }
    float m = fmaxf(acc0, acc1);
    #pragma unroll
    for (int s = 16; s > 0; s >>= 1) m = fmaxf(m, __shfl_xor_sync(0xffffffffu, m, s));
    float e0 = __expf(acc0 - m), e1 = __expf(acc1 - m);
    float s = e0 + e1;
    #pragma unroll
    for (int d = 16; d > 0; d >>= 1) s += __shfl_xor_sync(0xffffffffu, s, d);
    float inv = __fdividef(1.0f, s);
    out[row * ODIM + c0] = e0 * inv;
    out[row * ODIM + c1] = e1 * inv;
}

// ---------------- launch ----------------
extern "C" void kernel_launch(void* const* d_in, const int* in_sizes, int n_in,
                              void* d_out, int out_size) {
    const float* agent_state = (const float*)d_in[0];
    const float* goal_state  = (const float*)d_in[1];
    const int*   groups      = (const int*)  d_in[2];
    const float* W_goal      = (const float*)d_in[3];
    const float* b_goal      = (const float*)d_in[4];
    const float* W_g1        = (const float*)d_in[5];
    const float* b_g1        = (const float*)d_in[6];
    const float* W_g2        = (const float*)d_in[7];
    const float* b_g2        = (const float*)d_in[8];
    const float* W_ih        = (const float*)d_in[9];
    const float* W_hh        = (const float*)d_in[10];
    const float* b_lstm      = (const float*)d_in[11];
    const float* W_act       = (const float*)d_in[12];
    const float* b_act       = (const float*)d_in[13];
    float* out = (float*)d_out;

    float *X, *Y, *R, *ZS, *HS; int* RI;
    cudaGetSymbolAddress((void**)&X,  g_X);
    cudaGetSymbolAddress((void**)&Y,  g_Y);
    cudaGetSymbolAddress((void**)&R,  g_R);
    cudaGetSymbolAddress((void**)&ZS, g_zs);
    cudaGetSymbolAddress((void**)&HS, g_hs);
    cudaGetSymbolAddress((void**)&RI, g_rowidx);

    k_goal<<<1, 256>>>(goal_state, W_goal, b_goal, R);
    k_rowidx_init<<<NAGENTS / 256, 256>>>(RI);
    k_rowidx_scatter<<<NGROUPS * GSIZE / 256, 256>>>(groups, RI);

    k_group<1><<<NGROUPS, 256>>>(agent_state, groups, X);                 // U1
    k_gemm<<<dim3(4, 512), 256>>>(X, W_g1, b_g1, Y, NAGENTS, HDIM, HDIM, 1);   // H1
    k_group<0><<<NGROUPS, 256>>>(Y, nullptr, X);                          // U2
    k_gemm<<<dim3(4, 512), 256>>>(X, W_g2, b_g2, Y, NAGENTS, HDIM, HDIM, 1);   // H2
    k_pool<<<NGROUPS, 256>>>(Y, R);

    k_gemm<<<dim3(16, 17), 256>>>(R, W_ih, b_lstm, ZS, ZROWS, 1024, HDIM, 0);  // zs

    // 16-CTA cluster LSTM (nonportable cluster size)
    cudaFuncSetAttribute(k_lstm, cudaFuncAttributeNonPortableClusterSizeAllowed, 1);
    {
        cudaLaunchConfig_t cfg = {};
        cfg.gridDim  = dim3(16, 1, 1);
        cfg.blockDim = dim3(512, 1, 1);
        cfg.dynamicSmemBytes = 0;
        cfg.stream = 0;
        cudaLaunchAttribute at[1];
        at[0].id = cudaLaunchAttributeClusterDimension;
        at[0].val.clusterDim.x = 16;
        at[0].val.clusterDim.y = 1;
        at[0].val.clusterDim.z = 1;
        cfg.attrs = at;
        cfg.numAttrs = 1;
        cudaLaunchKernelEx(&cfg, k_lstm, (const float*)ZS, (const int*)RI, W_hh, (float*)HS);
    }

    k_out<<<(TSTEPS + 7) / 8, 256>>>(HS, W_act, b_act, out);
}

// round 14
// speedup vs baseline: 1.5994x; 1.5994x over previous
#include <cuda_runtime.h>
#include <cuda_bf16.h>
#include <cstdint>

#define NAGENTS 32768
#define HDIM    256
#define ODIM    64
#define NGROUPS 1024
#define GSIZE   32
#define TSTEPS  (NAGENTS + 1)
#define ZROWS   1026   /* 1024 pooled + goal + zero-feat row */

// ---------------- device scratch (allocation-free) ----------------
__device__ float g_X[NAGENTS * HDIM];
__device__ float g_Y[NAGENTS * HDIM];
__device__ float g_R[ZROWS * HDIM];          // rows: pooled[0..1023], goal_emb, zeros
__device__ float g_zs[ZROWS * 1024];         // distinct input projections (+bias)
__device__ float g_hs[TSTEPS * HDIM];        // all hidden states
__device__ int   g_rowidx[NAGENTS];

// ---------------- PTX helpers ----------------
__device__ __forceinline__ uint32_t smem_u32(const void* p) {
    return (uint32_t)__cvta_generic_to_shared(p);
}
__device__ __forceinline__ uint32_t mapa_u32(uint32_t addr, uint32_t rank) {
    uint32_t r;
    asm("mapa.shared::cluster.u32 %0, %1, %2;" : "=r"(r) : "r"(addr), "r"(rank));
    return r;
}
__device__ __forceinline__ void st_async_b64(uint32_t daddr, unsigned long long val,
                                             uint32_t dbar) {
    asm volatile("st.async.shared::cluster.mbarrier::complete_tx::bytes.b64 [%0], %1, [%2];"
                 :: "r"(daddr), "l"(val), "r"(dbar) : "memory");
}
__device__ __forceinline__ void mbar_init(uint32_t addr, uint32_t cnt) {
    asm volatile("mbarrier.init.shared.b64 [%0], %1;" :: "r"(addr), "r"(cnt) : "memory");
}
__device__ __forceinline__ void mbar_arrive_expect_tx(uint32_t addr, uint32_t bytes) {
    asm volatile("mbarrier.arrive.expect_tx.shared.b64 _, [%0], %1;"
                 :: "r"(addr), "r"(bytes) : "memory");
}
// CTA-scope acquire wait: st.async commits remote data to OUR smem before
// complete_tx is counted; acquire.cta orders our subsequent ld.shared.
__device__ __forceinline__ void mbar_wait(uint32_t addr, uint32_t parity) {
    asm volatile(
        "{\n\t.reg .pred P;\n\t"
        "WL_%=:\n\t"
        "mbarrier.try_wait.parity.acquire.cta.shared::cta.b64 P, [%0], %1, 0x989680;\n\t"
        "@P bra.uni WD_%=;\n\t"
        "bra.uni WL_%=;\n\t"
        "WD_%=:\n\t}"
        :: "r"(addr), "r"(parity) : "memory");
}
__device__ __forceinline__ uint32_t ctarank() {
    uint32_t r; asm("mov.u32 %0, %%cluster_ctarank;" : "=r"(r)); return r;
}
// Fast gates via single-op MUFU.TANH (tanh.approx.f32, sm_75+).
// sigmoid(x) = 0.5*tanh(x/2) + 0.5.
__device__ __forceinline__ float ftanh_fast(float x) {
    float y;
    asm("tanh.approx.f32 %0, %1;" : "=f"(y) : "f"(x));
    return y;
}
__device__ __forceinline__ float fsig_fast(float x) {
    float y;
    asm("tanh.approx.f32 %0, %1;" : "=f"(y) : "f"(x * 0.5f));
    return fmaf(0.5f, y, 0.5f);
}
// packed f32x2 FMA (SASS FFMA2 — only reachable via PTX)
#define FFMA2(acc, a, b) \
    asm("fma.rn.f32x2 %0, %1, %2, %3;" : "=l"(acc) : "l"(a), "l"(b), "l"(acc))
__device__ __forceinline__ unsigned long long pack_f32x2(float lo, float hi) {
    unsigned long long r;
    asm("mov.b64 %0, {%1, %2};" : "=l"(r) : "r"(__float_as_uint(lo)), "r"(__float_as_uint(hi)));
    return r;
}
__device__ __forceinline__ float2 unpack_f32x2(unsigned long long v) {
    uint32_t lo, hi;
    asm("mov.b64 {%0, %1}, %2;" : "=r"(lo), "=r"(hi) : "l"(v));
    return make_float2(__uint_as_float(lo), __uint_as_float(hi));
}

// ---------------- goal embedding ----------------
__global__ void k_goal(const float* __restrict__ goal, const float* __restrict__ W,
                       const float* __restrict__ b, float* __restrict__ R) {
    __shared__ float gs[HDIM];
    int j = threadIdx.x;
    gs[j] = goal[j];
    __syncthreads();
    float acc = 0.f;
    #pragma unroll 8
    for (int k = 0; k < HDIM; k++) acc = fmaf(gs[k], W[k * HDIM + j], acc);
    R[1024 * HDIM + j] = fmaxf(acc + b[j], 0.f);
    R[1025 * HDIM + j] = 0.f;
}

// ---------------- rowidx ----------------
__global__ void k_rowidx_init(int* __restrict__ ri) {
    int i = blockIdx.x * blockDim.x + threadIdx.x;
    if (i < NAGENTS) ri[i] = 1025;
}
__global__ void k_rowidx_scatter(const int* __restrict__ groups, int* __restrict__ ri) {
    int e = blockIdx.x * blockDim.x + threadIdx.x;
    if (e < NGROUPS * GSIZE) ri[groups[e]] = e >> 5;
}

// ---------------- group aggregate ----------------
template <int GATHER>
__global__ void k_group(const float* __restrict__ src, const int* __restrict__ groups,
                        float* __restrict__ U) {
    __shared__ float rows[GSIZE][HDIM];
    __shared__ int   idx[GSIZE];
    int g = blockIdx.x, t = threadIdx.x;
    if (GATHER) {
        if (t < GSIZE) idx[t] = groups[g * GSIZE + t];
        __syncthreads();
    }
    #pragma unroll 4
    for (int m = 0; m < GSIZE; m++) {
        int r = GATHER ? idx[m] : (g * GSIZE + m);
        rows[m][t] = src[r * HDIM + t];
    }
    __syncthreads();
    float s = 0.f;
    #pragma unroll
    for (int m = 0; m < GSIZE; m++) s += rows[m][t];
    const float inv = 1.0f / 33.0f;
    #pragma unroll 4
    for (int m = 0; m < GSIZE; m++)
        U[(g * GSIZE + m) * HDIM + t] = (rows[m][t] + s) * inv;
}

// ---------------- pool ----------------
__global__ void k_pool(const float* __restrict__ H2, float* __restrict__ R) {
    int g = blockIdx.x, t = threadIdx.x;
    float s = 0.f;
    #pragma unroll
    for (int m = 0; m < GSIZE; m++) s += H2[(g * GSIZE + m) * HDIM + t];
    R[g * HDIM + t] = s * (1.0f / 32.0f);
}

// ---------------- tiled SGEMM: C = act(A[M,K]@B[K,N] + bias) ----------------
__global__ __launch_bounds__(256) void k_gemm(
    const float* __restrict__ A, const float* __restrict__ B,
    const float* __restrict__ bias, float* __restrict__ C,
    int M, int N, int K, int doRelu)
{
    __shared__ float As[64][20];
    __shared__ float Bs[16][64];
    int t = threadIdx.x;
    int tx = t & 15, ty = t >> 4;
    int bm = blockIdx.y * 64, bn = blockIdx.x * 64;
    int row0 = ty * 4, col0 = tx * 4;
    float acc[4][4];
    #pragma unroll
    for (int i = 0; i < 4; i++)
        #pragma unroll
        for (int j = 0; j < 4; j++) acc[i][j] = 0.f;

    int am = t >> 2, ak4 = (t & 3) * 4;
    for (int kb = 0; kb < K; kb += 16) {
        float4 av = make_float4(0.f, 0.f, 0.f, 0.f);
        if (bm + am < M)
            av = *reinterpret_cast<const float4*>(&A[(size_t)(bm + am) * K + kb + ak4]);
        *reinterpret_cast<float4*>(&As[am][ak4]) = av;
        #pragma unroll
        for (int i = 0; i < 4; i++) {
            int e = t + i * 256;
            int k = e >> 6, n = e & 63;
            Bs[k][n] = B[(size_t)(kb + k) * N + bn + n];
        }
        __syncthreads();
        #pragma unroll
        for (int k = 0; k < 16; k++) {
            float a0 = As[row0 + 0][k], a1 = As[row0 + 1][k];
            float a2 = As[row0 + 2][k], a3 = As[row0 + 3][k];
            float4 bv = *reinterpret_cast<const float4*>(&Bs[k][col0]);
            acc[0][0] = fmaf(a0, bv.x, acc[0][0]); acc[0][1] = fmaf(a0, bv.y, acc[0][1]);
            acc[0][2] = fmaf(a0, bv.z, acc[0][2]); acc[0][3] = fmaf(a0, bv.w, acc[0][3]);
            acc[1][0] = fmaf(a1, bv.x, acc[1][0]); acc[1][1] = fmaf(a1, bv.y, acc[1][1]);
            acc[1][2] = fmaf(a1, bv.z, acc[1][2]); acc[1][3] = fmaf(a1, bv.w, acc[1][3]);
            acc[2][0] = fmaf(a2, bv.x, acc[2][0]); acc[2][1] = fmaf(a2, bv.y, acc[2][1]);
            acc[2][2] = fmaf(a2, bv.z, acc[2][2]); acc[2][3] = fmaf(a2, bv.w, acc[2][3]);
            acc[3][0] = fmaf(a3, bv.x, acc[3][0]); acc[3][1] = fmaf(a3, bv.y, acc[3][1]);
            acc[3][2] = fmaf(a3, bv.z, acc[3][2]); acc[3][3] = fmaf(a3, bv.w, acc[3][3]);
        }
        __syncthreads();
    }
    #pragma unroll
    for (int i = 0; i < 4; i++) {
        int r = bm + row0 + i;
        if (r >= M) break;
        #pragma unroll
        for (int j = 0; j < 4; j++) {
            float v = acc[i][j] + bias[bn + col0 + j];
            if (doRelu) v = fmaxf(v, 0.f);
            C[(size_t)r * N + bn + col0 + j] = v;
        }
    }
}

// ---------------- persistent 16-CTA-cluster LSTM (b64 fan-out: 128 txs/step) -----------
// CTA r owns hidden indices [r*16, r*16+16) and gate cols {g*256 + r*16 + j}.
// 512 threads: warp w lane l -> local col lc = w*4+(l&3) (64 cols), k-slice l>>2 (8x32k).
// Exchange: thread t<128 owns the col PAIR (2*(t&7), 2*(t&7)+1) for dest rank t>>3,
// tracks two cell states, computes both gate sets, packs (h0,h1) -> ONE st.async.b64.
// Dest barrier receives 128 tx updates/step instead of 256.
#define HPAD    36
#define HBUFW   (8 * HPAD)          /* 288 words */
#define HBYTES  (HBUFW * 4)         /* 1152 B    */
#define BAROFF  (2 * HBYTES)        /* 2304      */
#define PAOFF   (BAROFF + 16)       /* 2320      */
#define SMBYTES (PAOFF + 2 * 64 * 4)

__global__ __launch_bounds__(512, 1)
void k_lstm(const float* __restrict__ zs, const int* __restrict__ rowidx,
            const float* __restrict__ W_hh, float* __restrict__ hs)
{
    __shared__ __align__(16) unsigned char sm[SMBYTES];
    float* smf = reinterpret_cast<float*>(sm);

    const int t = threadIdx.x;
    const int l = t & 31;
    const int w = t >> 5;
    const int lc   = w * 4 + (l & 3);   // local gate-col 0..63
    const int ksl  = l >> 2;            // k-slice 0..7 (32 k each)
    const int gate = lc >> 4;
    const int j    = lc & 15;
    const uint32_t rank = ctarank();
    const int base = rank * 16;
    const int gcol = gate * 256 + base + j;

    // resident packed W_hh slice: 16 f32x2 regs (32 k-values for this col)
    unsigned long long w2[16];
    #pragma unroll
    for (int q = 0; q < 16; q++)
        w2[q] = pack_f32x2(W_hh[(size_t)(ksl * 32 + 2 * q) * 1024 + gcol],
                           W_hh[(size_t)(ksl * 32 + 2 * q + 1) * 1024 + gcol]);

    // zero both h buffers (incl. padding)
    for (int i = t; i < 2 * HBUFW; i += 512) smf[i] = 0.f;

    const uint32_t smb = smem_u32(sm);
    if (t == 0) {
        mbar_init(smb + BAROFF, 1);
        mbar_init(smb + BAROFF + 8, 1);
        mbar_arrive_expect_tx(smb + BAROFF, 1024);      // 16 CTAs x 8 x 8B
        mbar_arrive_expect_tx(smb + BAROFF + 8, 1024);
        asm volatile("fence.mbarrier_init.release.cluster;" ::: "memory");
    }
    __syncthreads();
    asm volatile("barrier.cluster.arrive.aligned;" ::: "memory");
    asm volatile("barrier.cluster.wait.aligned;" ::: "memory");

    // fan-out: thread t<128 owns col pair pc0=2*(t&7), pc0+1; dest rank = t>>3.
    // 8 lanes of a quarter-warp -> same rank, contiguous b64 words -> coalesced.
    const int pr  = t & 7;
    const int pc0 = pr * 2;
    uint32_t rdst = 0;
    if (t < 128) rdst = mapa_u32(smb, (uint32_t)(t >> 3));
    // padded word offset of global h idx (base+pc0) inside any h buffer
    // (pc0 even -> 8B aligned within the 32-block)
    const uint32_t myoff = 4u * ((rank >> 1) * HPAD + (rank & 1) * 16 + (uint32_t)pc0);

    float cA = 0.f, cB = 0.f;      // cell states for cols base+pc0, base+pc0+1
    uint32_t ph0 = 0, ph1 = 0;

    for (int step = 0; step < TSTEPS; step++) {
        // prefetch z gate values for both cols (hidden under the wait's poll)
        float zA0 = 0.f, zA1 = 0.f, zA2 = 0.f, zA3 = 0.f;
        float zB0 = 0.f, zB1 = 0.f, zB2 = 0.f, zB3 = 0.f;
        if (t < 128) {
            int row = (step == NAGENTS) ? 1024 : __ldg(&rowidx[step]);
            const float* zr = zs + (size_t)row * 1024 + base + pc0;
            zA0 = __ldg(zr);       zB0 = __ldg(zr + 1);
            zA1 = __ldg(zr + 256); zB1 = __ldg(zr + 257);
            zA2 = __ldg(zr + 512); zB2 = __ldg(zr + 513);
            zA3 = __ldg(zr + 768); zB3 = __ldg(zr + 769);
        }

        const int buf = step & 1;
        if (step > 0) {            // wait for h(step-1) fan-in (CTA-scope acquire)
            if (buf) { mbar_wait(smb + BAROFF + 8, ph1); ph1 ^= 1; }
            else     { mbar_wait(smb + BAROFF, ph0); ph0 ^= 1; }
            if (t == 0) mbar_arrive_expect_tx(smb + BAROFF + (buf ? 8 : 0), 1024);
        }

        // matvec: 32 k for (col, slice); padded slices (144B apart) -> conflict-free LDS.128
        const ulonglong2* hp = reinterpret_cast<const ulonglong2*>(
            sm + buf * HBYTES + ksl * (HPAD * 4));
        unsigned long long a0 = 0ull, a1 = 0ull;
        #pragma unroll
        for (int q = 0; q < 4; q++) {
            ulonglong2 ha = hp[2 * q];
            ulonglong2 hb = hp[2 * q + 1];
            FFMA2(a0, ha.x, w2[4 * q + 0]);
            FFMA2(a1, ha.y, w2[4 * q + 1]);
            FFMA2(a0, hb.x, w2[4 * q + 2]);
            FFMA2(a1, hb.y, w2[4 * q + 3]);
        }
        float2 f0 = unpack_f32x2(a0), f1 = unpack_f32x2(a1);
        float v = (f0.x + f0.y) + (f1.x + f1.y);
        // reduce across the 8 k-slices (lane bits 2,3,4)
        v += __shfl_xor_sync(0xffffffffu, v, 4);
        v += __shfl_xor_sync(0xffffffffu, v, 8);
        v += __shfl_xor_sync(0xffffffffu, v, 16);
        if (l < 4) smf[(PAOFF >> 2) + buf * 64 + j * 4 + gate] = v;  // pa[buf][j][gate]
        __syncthreads();                                              // one bar per step

        if (t < 128) {
            const float* pab = &smf[(PAOFF >> 2) + buf * 64];
            float4 gA = *reinterpret_cast<const float4*>(pab + pc0 * 4);
            float4 gB = *reinterpret_cast<const float4*>(pab + pc0 * 4 + 4);
            // two independent gate chains (ILP)
            cA = fsig_fast(gA.y + zA1) * cA + fsig_fast(gA.x + zA0) * ftanh_fast(gA.z + zA2);
            cB = fsig_fast(gB.y + zB1) * cB + fsig_fast(gB.x + zB0) * ftanh_fast(gB.z + zB2);
            float hA = fsig_fast(gA.w + zA3) * ftanh_fast(cA);
            float hB = fsig_fast(gB.w + zB3) * ftanh_fast(cB);
            if (step + 1 < TSTEPS) {       // 128 threads: one st.async.b64 each
                uint32_t nb = (uint32_t)((step + 1) & 1);
                st_async_b64(rdst + nb * HBYTES + myoff, pack_f32x2(hA, hB),
                             rdst + BAROFF + nb * 8u);
            }
            if (t < 8)
                *reinterpret_cast<float2*>(&hs[step * HDIM + base + pc0]) =
                    make_float2(hA, hB);
        }
    }
}

// ---------------- output: softmax(hs@W_act + b_act) ----------------
__global__ __launch_bounds__(256) void k_out(const float* __restrict__ hs,
                                             const float* __restrict__ W,
                                             const float* __restrict__ b,
                                             float* __restrict__ out) {
    __shared__ float hrow[8][HDIM];
    int warp = threadIdx.x >> 5, lane = threadIdx.x & 31;
    int row = blockIdx.x * 8 + warp;
    if (row >= TSTEPS) return;
    #pragma unroll
    for (int q = 0; q < 8; q++)
        hrow[warp][lane + q * 32] = hs[row * HDIM + lane + q * 32];
    __syncwarp();
    int c0 = lane, c1 = lane + 32;
    float acc0 = b[c0], acc1 = b[c1];
    #pragma unroll 8
    for (int k = 0; k < HDIM; k++) {
        float h = hrow[warp][k];
        acc0 = fmaf(h, __ldg(&W[k * ODIM + c0]), acc0);
        acc1 = fmaf(h, __ldg(&W[k * ODIM + c1]), acc1);
    }
    float m = fmaxf(acc0, acc1);
    #pragma unroll
    for (int s = 16; s > 0; s >>= 1) m = fmaxf(m, __shfl_xor_sync(0xffffffffu, m, s));
    float e0 = __expf(acc0 - m), e1 = __expf(acc1 - m);
    float s = e0 + e1;
    #pragma unroll
    for (int d = 16; d > 0; d >>= 1) s += __shfl_xor_sync(0xffffffffu, s, d);
    float inv = __fdividef(1.0f, s);
    out[row * ODIM + c0] = e0 * inv;
    out[row * ODIM + c1] = e1 * inv;
}

// ---------------- launch ----------------
extern "C" void kernel_launch(void* const* d_in, const int* in_sizes, int n_in,
                              void* d_out, int out_size) {
    const float* agent_state = (const float*)d_in[0];
    const float* goal_state  = (const float*)d_in[1];
    const int*   groups      = (const int*)  d_in[2];
    const float* W_goal      = (const float*)d_in[3];
    const float* b_goal      = (const float*)d_in[4];
    const float* W_g1        = (const float*)d_in[5];
    const float* b_g1        = (const float*)d_in[6];
    const float* W_g2        = (const float*)d_in[7];
    const float* b_g2        = (const float*)d_in[8];
    const float* W_ih        = (const float*)d_in[9];
    const float* W_hh        = (const float*)d_in[10];
    const float* b_lstm      = (const float*)d_in[11];
    const float* W_act       = (const float*)d_in[12];
    const float* b_act       = (const float*)d_in[13];
    float* out = (float*)d_out;

    float *X, *Y, *R, *ZS, *HS; int* RI;
    cudaGetSymbolAddress((void**)&X,  g_X);
    cudaGetSymbolAddress((void**)&Y,  g_Y);
    cudaGetSymbolAddress((void**)&R,  g_R);
    cudaGetSymbolAddress((void**)&ZS, g_zs);
    cudaGetSymbolAddress((void**)&HS, g_hs);
    cudaGetSymbolAddress((void**)&RI, g_rowidx);

    k_goal<<<1, 256>>>(goal_state, W_goal, b_goal, R);
    k_rowidx_init<<<NAGENTS / 256, 256>>>(RI);
    k_rowidx_scatter<<<NGROUPS * GSIZE / 256, 256>>>(groups, RI);

    k_group<1><<<NGROUPS, 256>>>(agent_state, groups, X);                 // U1
    k_gemm<<<dim3(4, 512), 256>>>(X, W_g1, b_g1, Y, NAGENTS, HDIM, HDIM, 1);   // H1
    k_group<0><<<NGROUPS, 256>>>(Y, nullptr, X);                          // U2
    k_gemm<<<dim3(4, 512), 256>>>(X, W_g2, b_g2, Y, NAGENTS, HDIM, HDIM, 1);   // H2
    k_pool<<<NGROUPS, 256>>>(Y, R);

    k_gemm<<<dim3(16, 17), 256>>>(R, W_ih, b_lstm, ZS, ZROWS, 1024, HDIM, 0);  // zs

    // 16-CTA cluster LSTM (nonportable cluster size)
    cudaFuncSetAttribute(k_lstm, cudaFuncAttributeNonPortableClusterSizeAllowed, 1);
    {
        cudaLaunchConfig_t cfg = {};
        cfg.gridDim  = dim3(16, 1, 1);
        cfg.blockDim = dim3(512, 1, 1);
        cfg.dynamicSmemBytes = 0;
        cfg.stream = 0;
        cudaLaunchAttribute at[1];
        at[0].id = cudaLaunchAttributeClusterDimension;
        at[0].val.clusterDim.x = 16;
        at[0].val.clusterDim.y = 1;
        at[0].val.clusterDim.z = 1;
        cfg.attrs = at;
        cfg.numAttrs = 1;
        cudaLaunchKernelEx(&cfg, k_lstm, (const float*)ZS, (const int*)RI, W_hh, (float*)HS);
    }

    k_out<<<(TSTEPS + 7) / 8, 256>>>(HS, W_act, b_act, out);
}

// round 15
// speedup vs baseline: 1.7504x; 1.0944x over previous
#include <cuda_runtime.h>
#include <cuda_bf16.h>
#include <cstdint>

#define NAGENTS 32768
#define HDIM    256
#define ODIM    64
#define NGROUPS 1024
#define GSIZE   32
#define TSTEPS  (NAGENTS + 1)
#define ZROWS   1026   /* 1024 pooled + goal + zero-feat row */

// ---------------- device scratch (allocation-free) ----------------
__device__ float g_X[NAGENTS * HDIM];
__device__ float g_Y[NAGENTS * HDIM];
__device__ float g_R[ZROWS * HDIM];          // rows: pooled[0..1023], goal_emb, zeros
__device__ float g_zs[ZROWS * 1024];         // distinct input projections (+bias)
__device__ float g_hs[TSTEPS * HDIM];        // all hidden states
__device__ int   g_rowidx[NAGENTS];

// ---------------- PTX helpers ----------------
__device__ __forceinline__ uint32_t smem_u32(const void* p) {
    return (uint32_t)__cvta_generic_to_shared(p);
}
__device__ __forceinline__ uint32_t mapa_u32(uint32_t addr, uint32_t rank) {
    uint32_t r;
    asm("mapa.shared::cluster.u32 %0, %1, %2;" : "=r"(r) : "r"(addr), "r"(rank));
    return r;
}
__device__ __forceinline__ void st_async_b32(uint32_t daddr, uint32_t val, uint32_t dbar) {
    asm volatile("st.async.shared::cluster.mbarrier::complete_tx::bytes.b32 [%0], %1, [%2];"
                 :: "r"(daddr), "r"(val), "r"(dbar) : "memory");
}
__device__ __forceinline__ void mbar_init(uint32_t addr, uint32_t cnt) {
    asm volatile("mbarrier.init.shared.b64 [%0], %1;" :: "r"(addr), "r"(cnt) : "memory");
}
__device__ __forceinline__ void mbar_arrive_expect_tx(uint32_t addr, uint32_t bytes) {
    asm volatile("mbarrier.arrive.expect_tx.shared.b64 _, [%0], %1;"
                 :: "r"(addr), "r"(bytes) : "memory");
}
// CTA-scope acquire wait: st.async commits remote data to OUR smem before
// complete_tx is counted; acquire.cta orders our subsequent ld.shared.
__device__ __forceinline__ void mbar_wait(uint32_t addr, uint32_t parity) {
    asm volatile(
        "{\n\t.reg .pred P;\n\t"
        "WL_%=:\n\t"
        "mbarrier.try_wait.parity.acquire.cta.shared::cta.b64 P, [%0], %1, 0x989680;\n\t"
        "@P bra.uni WD_%=;\n\t"
        "bra.uni WL_%=;\n\t"
        "WD_%=:\n\t}"
        :: "r"(addr), "r"(parity) : "memory");
}
__device__ __forceinline__ uint32_t ctarank() {
    uint32_t r; asm("mov.u32 %0, %%cluster_ctarank;" : "=r"(r)); return r;
}
// Fast gates via single-op MUFU.TANH (tanh.approx.f32, sm_75+).
__device__ __forceinline__ float ftanh_fast(float x) {
    float y;
    asm("tanh.approx.f32 %0, %1;" : "=f"(y) : "f"(x));
    return y;
}
// packed f32x2 FMA (SASS FFMA2 — only reachable via PTX)
#define FFMA2(acc, a, b) \
    asm("fma.rn.f32x2 %0, %1, %2, %3;" : "=l"(acc) : "l"(a), "l"(b), "l"(acc))
__device__ __forceinline__ unsigned long long pack_f32x2(float lo, float hi) {
    unsigned long long r;
    asm("mov.b64 %0, {%1, %2};" : "=l"(r) : "r"(__float_as_uint(lo)), "r"(__float_as_uint(hi)));
    return r;
}
__device__ __forceinline__ float2 unpack_f32x2(unsigned long long v) {
    uint32_t lo, hi;
    asm("mov.b64 {%0, %1}, %2;" : "=r"(lo), "=r"(hi) : "l"(v));
    return make_float2(__uint_as_float(lo), __uint_as_float(hi));
}

// ---------------- goal embedding ----------------
__global__ void k_goal(const float* __restrict__ goal, const float* __restrict__ W,
                       const float* __restrict__ b, float* __restrict__ R) {
    __shared__ float gs[HDIM];
    int j = threadIdx.x;
    gs[j] = goal[j];
    __syncthreads();
    float acc = 0.f;
    #pragma unroll 8
    for (int k = 0; k < HDIM; k++) acc = fmaf(gs[k], W[k * HDIM + j], acc);
    R[1024 * HDIM + j] = fmaxf(acc + b[j], 0.f);
    R[1025 * HDIM + j] = 0.f;
}

// ---------------- rowidx ----------------
__global__ void k_rowidx_init(int* __restrict__ ri) {
    int i = blockIdx.x * blockDim.x + threadIdx.x;
    if (i < NAGENTS) ri[i] = 1025;
}
__global__ void k_rowidx_scatter(const int* __restrict__ groups, int* __restrict__ ri) {
    int e = blockIdx.x * blockDim.x + threadIdx.x;
    if (e < NGROUPS * GSIZE) ri[groups[e]] = e >> 5;
}

// ---------------- group aggregate ----------------
template <int GATHER>
__global__ void k_group(const float* __restrict__ src, const int* __restrict__ groups,
                        float* __restrict__ U) {
    __shared__ float rows[GSIZE][HDIM];
    __shared__ int   idx[GSIZE];
    int g = blockIdx.x, t = threadIdx.x;
    if (GATHER) {
        if (t < GSIZE) idx[t] = groups[g * GSIZE + t];
        __syncthreads();
    }
    #pragma unroll 4
    for (int m = 0; m < GSIZE; m++) {
        int r = GATHER ? idx[m] : (g * GSIZE + m);
        rows[m][t] = src[r * HDIM + t];
    }
    __syncthreads();
    float s = 0.f;
    #pragma unroll
    for (int m = 0; m < GSIZE; m++) s += rows[m][t];
    const float inv = 1.0f / 33.0f;
    #pragma unroll 4
    for (int m = 0; m < GSIZE; m++)
        U[(g * GSIZE + m) * HDIM + t] = (rows[m][t] + s) * inv;
}

// ---------------- pool ----------------
__global__ void k_pool(const float* __restrict__ H2, float* __restrict__ R) {
    int g = blockIdx.x, t = threadIdx.x;
    float s = 0.f;
    #pragma unroll
    for (int m = 0; m < GSIZE; m++) s += H2[(g * GSIZE + m) * HDIM + t];
    R[g * HDIM + t] = s * (1.0f / 32.0f);
}

// ---------------- tiled SGEMM: C = act(A[M,K]@B[K,N] + bias) ----------------
__global__ __launch_bounds__(256) void k_gemm(
    const float* __restrict__ A, const float* __restrict__ B,
    const float* __restrict__ bias, float* __restrict__ C,
    int M, int N, int K, int doRelu)
{
    __shared__ float As[64][20];
    __shared__ float Bs[16][64];
    int t = threadIdx.x;
    int tx = t & 15, ty = t >> 4;
    int bm = blockIdx.y * 64, bn = blockIdx.x * 64;
    int row0 = ty * 4, col0 = tx * 4;
    float acc[4][4];
    #pragma unroll
    for (int i = 0; i < 4; i++)
        #pragma unroll
        for (int j = 0; j < 4; j++) acc[i][j] = 0.f;

    int am = t >> 2, ak4 = (t & 3) * 4;
    for (int kb = 0; kb < K; kb += 16) {
        float4 av = make_float4(0.f, 0.f, 0.f, 0.f);
        if (bm + am < M)
            av = *reinterpret_cast<const float4*>(&A[(size_t)(bm + am) * K + kb + ak4]);
        *reinterpret_cast<float4*>(&As[am][ak4]) = av;
        #pragma unroll
        for (int i = 0; i < 4; i++) {
            int e = t + i * 256;
            int k = e >> 6, n = e & 63;
            Bs[k][n] = B[(size_t)(kb + k) * N + bn + n];
        }
        __syncthreads();
        #pragma unroll
        for (int k = 0; k < 16; k++) {
            float a0 = As[row0 + 0][k], a1 = As[row0 + 1][k];
            float a2 = As[row0 + 2][k], a3 = As[row0 + 3][k];
            float4 bv = *reinterpret_cast<const float4*>(&Bs[k][col0]);
            acc[0][0] = fmaf(a0, bv.x, acc[0][0]); acc[0][1] = fmaf(a0, bv.y, acc[0][1]);
            acc[0][2] = fmaf(a0, bv.z, acc[0][2]); acc[0][3] = fmaf(a0, bv.w, acc[0][3]);
            acc[1][0] = fmaf(a1, bv.x, acc[1][0]); acc[1][1] = fmaf(a1, bv.y, acc[1][1]);
            acc[1][2] = fmaf(a1, bv.z, acc[1][2]); acc[1][3] = fmaf(a1, bv.w, acc[1][3]);
            acc[2][0] = fmaf(a2, bv.x, acc[2][0]); acc[2][1] = fmaf(a2, bv.y, acc[2][1]);
            acc[2][2] = fmaf(a2, bv.z, acc[2][2]); acc[2][3] = fmaf(a2, bv.w, acc[2][3]);
            acc[3][0] = fmaf(a3, bv.x, acc[3][0]); acc[3][1] = fmaf(a3, bv.y, acc[3][1]);
            acc[3][2] = fmaf(a3, bv.z, acc[3][2]); acc[3][3] = fmaf(a3, bv.w, acc[3][3]);
        }
        __syncthreads();
    }
    #pragma unroll
    for (int i = 0; i < 4; i++) {
        int r = bm + row0 + i;
        if (r >= M) break;
        #pragma unroll
        for (int j = 0; j < 4; j++) {
            float v = acc[i][j] + bias[bn + col0 + j];
            if (doRelu) v = fmaxf(v, 0.f);
            C[(size_t)r * N + bn + col0 + j] = v;
        }
    }
}

// ---------------- persistent 16-CTA-cluster LSTM (pre-activated gates) ----------------
// CTA r owns hidden indices [r*16, r*16+16) and gate cols {g*256 + r*16 + j}.
// 512 threads: warp w lane l -> local col lc = w*4+(l&3) (64 cols), k-slice l>>2 (8x32k).
// The l<4 reducer threads apply the gate nonlinearity BEFORE the barrier (one MUFU
// each, z folded in); post-barrier combiners do only mul+fma+tanh(c)+mul -> shortest
// possible serial segment between barrier and fan-out.
#define HPAD    36
#define HBUFW   (8 * HPAD)          /* 288 words */
#define HBYTES  (HBUFW * 4)         /* 1152 B    */
#define BAROFF  (2 * HBYTES)        /* 2304      */
#define PAOFF   (BAROFF + 16)       /* 2320      */
#define SMBYTES (PAOFF + 2 * 64 * 4)

__global__ __launch_bounds__(512, 1)
void k_lstm(const float* __restrict__ zs, const int* __restrict__ rowidx,
            const float* __restrict__ W_hh, float* __restrict__ hs)
{
    __shared__ __align__(16) unsigned char sm[SMBYTES];
    float* smf = reinterpret_cast<float*>(sm);

    const int t = threadIdx.x;
    const int l = t & 31;
    const int w = t >> 5;
    const int lc   = w * 4 + (l & 3);   // local gate-col 0..63
    const int ksl  = l >> 2;            // k-slice 0..7 (32 k each)
    const int gate = lc >> 4;
    const int j    = lc & 15;
    const uint32_t rank = ctarank();
    const int base = rank * 16;
    const int gcol = gate * 256 + base + j;

    // resident packed W_hh slice: 16 f32x2 regs (32 k-values for this col)
    unsigned long long w2[16];
    #pragma unroll
    for (int q = 0; q < 16; q++)
        w2[q] = pack_f32x2(W_hh[(size_t)(ksl * 32 + 2 * q) * 1024 + gcol],
                           W_hh[(size_t)(ksl * 32 + 2 * q + 1) * 1024 + gcol]);

    // zero both h buffers (incl. padding)
    for (int i = t; i < 2 * HBUFW; i += 512) smf[i] = 0.f;

    const uint32_t smb = smem_u32(sm);
    if (t == 0) {
        mbar_init(smb + BAROFF, 1);
        mbar_init(smb + BAROFF + 8, 1);
        mbar_arrive_expect_tx(smb + BAROFF, 1024);      // 16 CTAs x 16 floats
        mbar_arrive_expect_tx(smb + BAROFF + 8, 1024);
        asm volatile("fence.mbarrier_init.release.cluster;" ::: "memory");
    }
    __syncthreads();
    asm volatile("barrier.cluster.arrive.aligned;" ::: "memory");
    asm volatile("barrier.cluster.wait.aligned;" ::: "memory");

    // fan-out: thread t<256 owns col hj=t&15, sends to rank t>>4 (16 lanes of a
    // half-warp -> same rank, contiguous words -> coalesced 64B DSMEM writes)
    const int hj = t & 15;
    uint32_t rdst = 0;
    if (t < 256) rdst = mapa_u32(smb, (uint32_t)(t >> 4));
    // padded word offset of my h value (global idx base+hj) inside any h buffer
    const uint32_t myoff = 4u * ((rank >> 1) * HPAD + (rank & 1) * 16 + (uint32_t)hj);

    // gate-activation select constants for the l<4 reducer threads:
    // gates i,f,o: sigmoid(x)=0.5*tanh(0.5x)+0.5 ; gate g: tanh(x)
    const bool isG   = (gate == 2);
    const float xscl = isG ? 1.0f : 0.5f;

    float c = 0.f;                 // cell state for col base+hj (replicated x16 threads)
    uint32_t ph0 = 0, ph1 = 0;

    for (int step = 0; step < TSTEPS; step++) {
        // l<4 reducer threads: prefetch this col's z value (hidden under the wait)
        float zv = 0.f;
        if (l < 4) {
            int row = (step == NAGENTS) ? 1024 : __ldg(&rowidx[step]);
            zv = __ldg(&zs[(size_t)row * 1024 + gcol]);
        }

        const int buf = step & 1;
        if (step > 0) {            // wait for h(step-1) fan-in (CTA-scope acquire)
            if (buf) { mbar_wait(smb + BAROFF + 8, ph1); ph1 ^= 1; }
            else     { mbar_wait(smb + BAROFF, ph0); ph0 ^= 1; }
            if (t == 0) mbar_arrive_expect_tx(smb + BAROFF + (buf ? 8 : 0), 1024);
        }

        // matvec: 32 k for (col, slice); padded slices (144B apart) -> conflict-free LDS.128
        const ulonglong2* hp = reinterpret_cast<const ulonglong2*>(
            sm + buf * HBYTES + ksl * (HPAD * 4));
        unsigned long long a0 = 0ull, a1 = 0ull;
        #pragma unroll
        for (int q = 0; q < 4; q++) {
            ulonglong2 ha = hp[2 * q];
            ulonglong2 hb = hp[2 * q + 1];
            FFMA2(a0, ha.x, w2[4 * q + 0]);
            FFMA2(a1, ha.y, w2[4 * q + 1]);
            FFMA2(a0, hb.x, w2[4 * q + 2]);
            FFMA2(a1, hb.y, w2[4 * q + 3]);
        }
        float2 f0 = unpack_f32x2(a0), f1 = unpack_f32x2(a1);
        float v = (f0.x + f0.y) + (f1.x + f1.y);
        // reduce across the 8 k-slices (lane bits 2,3,4)
        v += __shfl_xor_sync(0xffffffffu, v, 4);
        v += __shfl_xor_sync(0xffffffffu, v, 8);
        v += __shfl_xor_sync(0xffffffffu, v, 16);
        if (l < 4) {
            // pre-activate: one MUFU here, off the post-barrier critical path
            float x = v + zv;
            float y = ftanh_fast(x * xscl);
            float a = isG ? y : fmaf(0.5f, y, 0.5f);
            smf[(PAOFF >> 2) + buf * 64 + j * 4 + gate] = a;   // pa[buf][j][gate]
        }
        __syncthreads();                                        // one bar per step

        if (t < 256) {
            float4 g4 = *reinterpret_cast<const float4*>(
                &smf[(PAOFF >> 2) + buf * 64 + hj * 4]);
            // g4 = (a_i, a_f, a_g, a_o), already activated
            c = fmaf(g4.y, c, g4.x * g4.z);
            float h = g4.w * ftanh_fast(c);
            if (step + 1 < TSTEPS) {       // each of 256 threads: one st.async
                uint32_t nb = (uint32_t)((step + 1) & 1);
                st_async_b32(rdst + nb * HBYTES + myoff, __float_as_uint(h),
                             rdst + BAROFF + nb * 8u);
            }
            if (t < 16) hs[step * HDIM + base + t] = h;
        }
    }
}

// ---------------- output: softmax(hs@W_act + b_act) ----------------
__global__ __launch_bounds__(256) void k_out(const float* __restrict__ hs,
                                             const float* __restrict__ W,
                                             const float* __restrict__ b,
                                             float* __restrict__ out) {
    __shared__ float hrow[8][HDIM];
    int warp = threadIdx.x >> 5, lane = threadIdx.x & 31;
    int row = blockIdx.x * 8 + warp;
    if (row >= TSTEPS) return;
    #pragma unroll
    for (int q = 0; q < 8; q++)
        hrow[warp][lane + q * 32] = hs[row * HDIM + lane + q * 32];
    __syncwarp();
    int c0 = lane, c1 = lane + 32;
    float acc0 = b[c0], acc1 = b[c1];
    #pragma unroll 8
    for (int k = 0; k < HDIM; k++) {
        float h = hrow[warp][k];
        acc0 = fmaf(h, __ldg(&W[k * ODIM + c0]), acc0);
        acc1 = fmaf(h, __ldg(&W[k * ODIM + c1]), acc1);
    }
    float m = fmaxf(acc0, acc1);
    #pragma unroll
    for (int s = 16; s > 0; s >>= 1) m = fmaxf(m, __shfl_xor_sync(0xffffffffu, m, s));
    float e0 = __expf(acc0 - m), e1 = __expf(acc1 - m);
    float s = e0 + e1;
    #pragma unroll
    for (int d = 16; d > 0; d >>= 1) s += __shfl_xor_sync(0xffffffffu, s, d);
    float inv = __fdividef(1.0f, s);
    out[row * ODIM + c0] = e0 * inv;
    out[row * ODIM + c1] = e1 * inv;
}

// ---------------- launch ----------------
extern "C" void kernel_launch(void* const* d_in, const int* in_sizes, int n_in,
                              void* d_out, int out_size) {
    const float* agent_state = (const float*)d_in[0];
    const float* goal_state  = (const float*)d_in[1];
    const int*   groups      = (const int*)  d_in[2];
    const float* W_goal      = (const float*)d_in[3];
    const float* b_goal      = (const float*)d_in[4];
    const float* W_g1        = (const float*)d_in[5];
    const float* b_g1        = (const float*)d_in[6];
    const float* W_g2        = (const float*)d_in[7];
    const float* b_g2        = (const float*)d_in[8];
    const float* W_ih        = (const float*)d_in[9];
    const float* W_hh        = (const float*)d_in[10];
    const float* b_lstm      = (const float*)d_in[11];
    const float* W_act       = (const float*)d_in[12];
    const float* b_act       = (const float*)d_in[13];
    float* out = (float*)d_out;

    float *X, *Y, *R, *ZS, *HS; int* RI;
    cudaGetSymbolAddress((void**)&X,  g_X);
    cudaGetSymbolAddress((void**)&Y,  g_Y);
    cudaGetSymbolAddress((void**)&R,  g_R);
    cudaGetSymbolAddress((void**)&ZS, g_zs);
    cudaGetSymbolAddress((void**)&HS, g_hs);
    cudaGetSymbolAddress((void**)&RI, g_rowidx);

    k_goal<<<1, 256>>>(goal_state, W_goal, b_goal, R);
    k_rowidx_init<<<NAGENTS / 256, 256>>>(RI);
    k_rowidx_scatter<<<NGROUPS * GSIZE / 256, 256>>>(groups, RI);

    k_group<1><<<NGROUPS, 256>>>(agent_state, groups, X);                 // U1
    k_gemm<<<dim3(4, 512), 256>>>(X, W_g1, b_g1, Y, NAGENTS, HDIM, HDIM, 1);   // H1
    k_group<0><<<NGROUPS, 256>>>(Y, nullptr, X);                          // U2
    k_gemm<<<dim3(4, 512), 256>>>(X, W_g2, b_g2, Y, NAGENTS, HDIM, HDIM, 1);   // H2
    k_pool<<<NGROUPS, 256>>>(Y, R);

    k_gemm<<<dim3(16, 17), 256>>>(R, W_ih, b_lstm, ZS, ZROWS, 1024, HDIM, 0);  // zs

    // 16-CTA cluster LSTM (nonportable cluster size)
    cudaFuncSetAttribute(k_lstm, cudaFuncAttributeNonPortableClusterSizeAllowed, 1);
    {
        cudaLaunchConfig_t cfg = {};
        cfg.gridDim  = dim3(16, 1, 1);
        cfg.blockDim = dim3(512, 1, 1);
        cfg.dynamicSmemBytes = 0;
        cfg.stream = 0;
        cudaLaunchAttribute at[1];
        at[0].id = cudaLaunchAttributeClusterDimension;
        at[0].val.clusterDim.x = 16;
        at[0].val.clusterDim.y = 1;
        at[0].val.clusterDim.z = 1;
        cfg.attrs = at;
        cfg.numAttrs = 1;
        cudaLaunchKernelEx(&cfg, k_lstm, (const float*)ZS, (const int*)RI, W_hh, (float*)HS);
    }

    k_out<<<(TSTEPS + 7) / 8, 256>>>(HS, W_act, b_act, out);
}

// round 16
// speedup vs baseline: 1.7665x; 1.0092x over previous
#include <cuda_runtime.h>
#include <cuda_bf16.h>
#include <cstdint>

#define NAGENTS 32768
#define HDIM    256
#define ODIM    64
#define NGROUPS 1024
#define GSIZE   32
#define TSTEPS  (NAGENTS + 1)
#define ZROWS   1026   /* 1024 pooled + goal + zero-feat row */

// ---------------- device scratch (allocation-free) ----------------
__device__ float g_X[NAGENTS * HDIM];
__device__ float g_Y[NAGENTS * HDIM];
__device__ float g_R[ZROWS * HDIM];          // rows: pooled[0..1023], goal_emb, zeros
__device__ float g_zs[ZROWS * 1024];         // distinct input projections (+bias)
__device__ float g_hs[TSTEPS * HDIM];        // all hidden states
__device__ int   g_rowidx[NAGENTS];

// ---------------- PTX helpers ----------------
__device__ __forceinline__ uint32_t smem_u32(const void* p) {
    return (uint32_t)__cvta_generic_to_shared(p);
}
__device__ __forceinline__ uint32_t mapa_u32(uint32_t addr, uint32_t rank) {
    uint32_t r;
    asm("mapa.shared::cluster.u32 %0, %1, %2;" : "=r"(r) : "r"(addr), "r"(rank));
    return r;
}
__device__ __forceinline__ void st_async_b32(uint32_t daddr, uint32_t val, uint32_t dbar) {
    asm volatile("st.async.shared::cluster.mbarrier::complete_tx::bytes.b32 [%0], %1, [%2];"
                 :: "r"(daddr), "r"(val), "r"(dbar) : "memory");
}
__device__ __forceinline__ void mbar_init(uint32_t addr, uint32_t cnt) {
    asm volatile("mbarrier.init.shared.b64 [%0], %1;" :: "r"(addr), "r"(cnt) : "memory");
}
__device__ __forceinline__ void mbar_arrive_expect_tx(uint32_t addr, uint32_t bytes) {
    asm volatile("mbarrier.arrive.expect_tx.shared.b64 _, [%0], %1;"
                 :: "r"(addr), "r"(bytes) : "memory");
}
// CTA-scope acquire wait: st.async commits remote data to OUR smem before
// complete_tx is counted; acquire.cta orders our subsequent ld.shared.
__device__ __forceinline__ void mbar_wait(uint32_t addr, uint32_t parity) {
    asm volatile(
        "{\n\t.reg .pred P;\n\t"
        "WL_%=:\n\t"
        "mbarrier.try_wait.parity.acquire.cta.shared::cta.b64 P, [%0], %1, 0x989680;\n\t"
        "@P bra.uni WD_%=;\n\t"
        "bra.uni WL_%=;\n\t"
        "WD_%=:\n\t}"
        :: "r"(addr), "r"(parity) : "memory");
}
__device__ __forceinline__ uint32_t ctarank() {
    uint32_t r; asm("mov.u32 %0, %%cluster_ctarank;" : "=r"(r)); return r;
}
// Fast gates via single-op MUFU.TANH (tanh.approx.f32, sm_75+).
__device__ __forceinline__ float ftanh_fast(float x) {
    float y;
    asm("tanh.approx.f32 %0, %1;" : "=f"(y) : "f"(x));
    return y;
}
// packed f32x2 FMA (SASS FFMA2 — only reachable via PTX)
#define FFMA2(acc, a, b) \
    asm("fma.rn.f32x2 %0, %1, %2, %3;" : "=l"(acc) : "l"(a), "l"(b), "l"(acc))
__device__ __forceinline__ unsigned long long pack_f32x2(float lo, float hi) {
    unsigned long long r;
    asm("mov.b64 %0, {%1, %2};" : "=l"(r) : "r"(__float_as_uint(lo)), "r"(__float_as_uint(hi)));
    return r;
}
__device__ __forceinline__ float2 unpack_f32x2(unsigned long long v) {
    uint32_t lo, hi;
    asm("mov.b64 {%0, %1}, %2;" : "=r"(lo), "=r"(hi) : "l"(v));
    return make_float2(__uint_as_float(lo), __uint_as_float(hi));
}

// ---------------- goal embedding ----------------
__global__ void k_goal(const float* __restrict__ goal, const float* __restrict__ W,
                       const float* __restrict__ b, float* __restrict__ R) {
    __shared__ float gs[HDIM];
    int j = threadIdx.x;
    gs[j] = goal[j];
    __syncthreads();
    float acc = 0.f;
    #pragma unroll 8
    for (int k = 0; k < HDIM; k++) acc = fmaf(gs[k], W[k * HDIM + j], acc);
    R[1024 * HDIM + j] = fmaxf(acc + b[j], 0.f);
    R[1025 * HDIM + j] = 0.f;
}

// ---------------- rowidx ----------------
__global__ void k_rowidx_init(int* __restrict__ ri) {
    int i = blockIdx.x * blockDim.x + threadIdx.x;
    if (i < NAGENTS) ri[i] = 1025;
}
__global__ void k_rowidx_scatter(const int* __restrict__ groups, int* __restrict__ ri) {
    int e = blockIdx.x * blockDim.x + threadIdx.x;
    if (e < NGROUPS * GSIZE) ri[groups[e]] = e >> 5;
}

// ---------------- group aggregate ----------------
template <int GATHER>
__global__ void k_group(const float* __restrict__ src, const int* __restrict__ groups,
                        float* __restrict__ U) {
    __shared__ float rows[GSIZE][HDIM];
    __shared__ int   idx[GSIZE];
    int g = blockIdx.x, t = threadIdx.x;
    if (GATHER) {
        if (t < GSIZE) idx[t] = groups[g * GSIZE + t];
        __syncthreads();
    }
    #pragma unroll 4
    for (int m = 0; m < GSIZE; m++) {
        int r = GATHER ? idx[m] : (g * GSIZE + m);
        rows[m][t] = src[r * HDIM + t];
    }
    __syncthreads();
    float s = 0.f;
    #pragma unroll
    for (int m = 0; m < GSIZE; m++) s += rows[m][t];
    const float inv = 1.0f / 33.0f;
    #pragma unroll 4
    for (int m = 0; m < GSIZE; m++)
        U[(g * GSIZE + m) * HDIM + t] = (rows[m][t] + s) * inv;
}

// ---------------- pool ----------------
__global__ void k_pool(const float* __restrict__ H2, float* __restrict__ R) {
    int g = blockIdx.x, t = threadIdx.x;
    float s = 0.f;
    #pragma unroll
    for (int m = 0; m < GSIZE; m++) s += H2[(g * GSIZE + m) * HDIM + t];
    R[g * HDIM + t] = s * (1.0f / 32.0f);
}

// ---------------- tiled SGEMM: C = act(A[M,K]@B[K,N] + bias) ----------------
__global__ __launch_bounds__(256) void k_gemm(
    const float* __restrict__ A, const float* __restrict__ B,
    const float* __restrict__ bias, float* __restrict__ C,
    int M, int N, int K, int doRelu)
{
    __shared__ float As[64][20];
    __shared__ float Bs[16][64];
    int t = threadIdx.x;
    int tx = t & 15, ty = t >> 4;
    int bm = blockIdx.y * 64, bn = blockIdx.x * 64;
    int row0 = ty * 4, col0 = tx * 4;
    float acc[4][4];
    #pragma unroll
    for (int i = 0; i < 4; i++)
        #pragma unroll
        for (int j = 0; j < 4; j++) acc[i][j] = 0.f;

    int am = t >> 2, ak4 = (t & 3) * 4;
    for (int kb = 0; kb < K; kb += 16) {
        float4 av = make_float4(0.f, 0.f, 0.f, 0.f);
        if (bm + am < M)
            av = *reinterpret_cast<const float4*>(&A[(size_t)(bm + am) * K + kb + ak4]);
        *reinterpret_cast<float4*>(&As[am][ak4]) = av;
        #pragma unroll
        for (int i = 0; i < 4; i++) {
            int e = t + i * 256;
            int k = e >> 6, n = e & 63;
            Bs[k][n] = B[(size_t)(kb + k) * N + bn + n];
        }
        __syncthreads();
        #pragma unroll
        for (int k = 0; k < 16; k++) {
            float a0 = As[row0 + 0][k], a1 = As[row0 + 1][k];
            float a2 = As[row0 + 2][k], a3 = As[row0 + 3][k];
            float4 bv = *reinterpret_cast<const float4*>(&Bs[k][col0]);
            acc[0][0] = fmaf(a0, bv.x, acc[0][0]); acc[0][1] = fmaf(a0, bv.y, acc[0][1]);
            acc[0][2] = fmaf(a0, bv.z, acc[0][2]); acc[0][3] = fmaf(a0, bv.w, acc[0][3]);
            acc[1][0] = fmaf(a1, bv.x, acc[1][0]); acc[1][1] = fmaf(a1, bv.y, acc[1][1]);
            acc[1][2] = fmaf(a1, bv.z, acc[1][2]); acc[1][3] = fmaf(a1, bv.w, acc[1][3]);
            acc[2][0] = fmaf(a2, bv.x, acc[2][0]); acc[2][1] = fmaf(a2, bv.y, acc[2][1]);
            acc[2][2] = fmaf(a2, bv.z, acc[2][2]); acc[2][3] = fmaf(a2, bv.w, acc[2][3]);
            acc[3][0] = fmaf(a3, bv.x, acc[3][0]); acc[3][1] = fmaf(a3, bv.y, acc[3][1]);
            acc[3][2] = fmaf(a3, bv.z, acc[3][2]); acc[3][3] = fmaf(a3, bv.w, acc[3][3]);
        }
        __syncthreads();
    }
    #pragma unroll
    for (int i = 0; i < 4; i++) {
        int r = bm + row0 + i;
        if (r >= M) break;
        #pragma unroll
        for (int j = 0; j < 4; j++) {
            float v = acc[i][j] + bias[bn + col0 + j];
            if (doRelu) v = fmaxf(v, 0.f);
            C[(size_t)r * N + bn + col0 + j] = v;
        }
    }
}

// ---------------- persistent 16-CTA-cluster LSTM (256 threads, 2-stage reduce) ----------
// CTA r owns hidden indices [r*16, r*16+16) and gate cols {g*256 + r*16 + j}.
// 256 threads: warp w (0..7) lane l -> local col lc = w*8+(l&7) (64 cols),
// k-slice l>>3 (4 slices x 64 k; each spans two padded 36-word blocks).
// Reduce = 2 shfl stages (lane bits 3,4). Reducers (l<8) pre-activate gates.
// Senders: all 256 threads, col hj=t&15 -> rank t>>4 (coalesced half-warp sends).
#define HPAD    36
#define HBUFW   (8 * HPAD)          /* 288 words */
#define HBYTES  (HBUFW * 4)         /* 1152 B    */
#define BAROFF  (2 * HBYTES)        /* 2304      */
#define PAOFF   (BAROFF + 16)       /* 2320      */
#define SMBYTES (PAOFF + 2 * 64 * 4)

__global__ __launch_bounds__(256, 1)
void k_lstm(const float* __restrict__ zs, const int* __restrict__ rowidx,
            const float* __restrict__ W_hh, float* __restrict__ hs)
{
    __shared__ __align__(16) unsigned char sm[SMBYTES];
    float* smf = reinterpret_cast<float*>(sm);

    const int t = threadIdx.x;
    const int l = t & 31;
    const int w = t >> 5;
    const int lc   = w * 8 + (l & 7);   // local gate-col 0..63
    const int ksl  = l >> 3;            // k-slice 0..3 (64 k each)
    const int gate = lc >> 4;
    const int j    = lc & 15;
    const uint32_t rank = ctarank();
    const int base = rank * 16;
    const int gcol = gate * 256 + base + j;
    const int k0   = ksl * 64;

    // resident packed W_hh slice: 32 f32x2 regs (64 k-values for this col)
    unsigned long long w2[32];
    #pragma unroll
    for (int q = 0; q < 32; q++)
        w2[q] = pack_f32x2(W_hh[(size_t)(k0 + 2 * q) * 1024 + gcol],
                           W_hh[(size_t)(k0 + 2 * q + 1) * 1024 + gcol]);

    // zero both h buffers (incl. padding)
    for (int i = t; i < 2 * HBUFW; i += 256) smf[i] = 0.f;

    const uint32_t smb = smem_u32(sm);
    if (t == 0) {
        mbar_init(smb + BAROFF, 1);
        mbar_init(smb + BAROFF + 8, 1);
        mbar_arrive_expect_tx(smb + BAROFF, 1024);      // 16 CTAs x 16 floats
        mbar_arrive_expect_tx(smb + BAROFF + 8, 1024);
        asm volatile("fence.mbarrier_init.release.cluster;" ::: "memory");
    }
    __syncthreads();
    asm volatile("barrier.cluster.arrive.aligned;" ::: "memory");
    asm volatile("barrier.cluster.wait.aligned;" ::: "memory");

    // fan-out: thread t owns col hj=t&15, sends to rank t>>4 (16 lanes of a
    // half-warp -> same rank, contiguous words -> coalesced 64B DSMEM writes)
    const int hj = t & 15;
    const uint32_t rdst = mapa_u32(smb, (uint32_t)(t >> 4));
    // padded word offset of my h value (global idx base+hj) inside any h buffer
    const uint32_t myoff = 4u * ((rank >> 1) * HPAD + (rank & 1) * 16 + (uint32_t)hj);

    // gate-activation select constants for the l<8 reducer threads:
    // gates i,f,o: sigmoid(x)=0.5*tanh(0.5x)+0.5 ; gate g: tanh(x)
    const bool isG   = (gate == 2);
    const float xscl = isG ? 1.0f : 0.5f;

    float c = 0.f;                 // cell state for col base+hj (replicated x16 threads)
    uint32_t ph0 = 0, ph1 = 0;

    for (int step = 0; step < TSTEPS; step++) {
        // l<8 reducer threads: prefetch this col's z value (hidden under the wait)
        float zv = 0.f;
        if (l < 8) {
            int row = (step == NAGENTS) ? 1024 : __ldg(&rowidx[step]);
            zv = __ldg(&zs[(size_t)row * 1024 + gcol]);
        }

        const int buf = step & 1;
        if (step > 0) {            // wait for h(step-1) fan-in (CTA-scope acquire)
            if (buf) { mbar_wait(smb + BAROFF + 8, ph1); ph1 ^= 1; }
            else     { mbar_wait(smb + BAROFF, ph0); ph0 ^= 1; }
            if (t == 0) mbar_arrive_expect_tx(smb + BAROFF + (buf ? 8 : 0), 1024);
        }

        // matvec: 64 k for (col, slice), split over the two padded 36-word blocks.
        // Per-LDS.128 bank audit: 4 slice bases 288B apart -> word ranges
        // {0,8,16,24}+[0..3] (first block) / {4,12,20,28}+[0..3] (second) — disjoint.
        const ulonglong2* hpA = reinterpret_cast<const ulonglong2*>(
            sm + buf * HBYTES + (2 * ksl) * (HPAD * 4));
        const ulonglong2* hpB = reinterpret_cast<const ulonglong2*>(
            sm + buf * HBYTES + (2 * ksl + 1) * (HPAD * 4));
        unsigned long long a0 = 0ull, a1 = 0ull, a2 = 0ull, a3 = 0ull;
        #pragma unroll
        for (int q = 0; q < 4; q++) {
            ulonglong2 ha = hpA[2 * q];
            ulonglong2 hb = hpA[2 * q + 1];
            FFMA2(a0, ha.x, w2[4 * q + 0]);
            FFMA2(a1, ha.y, w2[4 * q + 1]);
            FFMA2(a0, hb.x, w2[4 * q + 2]);
            FFMA2(a1, hb.y, w2[4 * q + 3]);
        }
        #pragma unroll
        for (int q = 0; q < 4; q++) {
            ulonglong2 ha = hpB[2 * q];
            ulonglong2 hb = hpB[2 * q + 1];
            FFMA2(a2, ha.x, w2[16 + 4 * q + 0]);
            FFMA2(a3, ha.y, w2[16 + 4 * q + 1]);
            FFMA2(a2, hb.x, w2[16 + 4 * q + 2]);
            FFMA2(a3, hb.y, w2[16 + 4 * q + 3]);
        }
        float2 f0 = unpack_f32x2(a0), f1 = unpack_f32x2(a1);
        float2 f2 = unpack_f32x2(a2), f3 = unpack_f32x2(a3);
        float v = ((f0.x + f0.y) + (f1.x + f1.y)) + ((f2.x + f2.y) + (f3.x + f3.y));
        // reduce across the 4 k-slices (lane bits 3,4) — 2 stages
        v += __shfl_xor_sync(0xffffffffu, v, 8);
        v += __shfl_xor_sync(0xffffffffu, v, 16);
        if (l < 8) {
            // pre-activate: one MUFU here, off the post-barrier critical path
            float x = v + zv;
            float y = ftanh_fast(x * xscl);
            float a = isG ? y : fmaf(0.5f, y, 0.5f);
            smf[(PAOFF >> 2) + buf * 64 + j * 4 + gate] = a;   // pa[buf][j][gate]
        }
        __syncthreads();                                        // one bar per step

        {
            float4 g4 = *reinterpret_cast<const float4*>(
                &smf[(PAOFF >> 2) + buf * 64 + hj * 4]);
            // g4 = (a_i, a_f, a_g, a_o), already activated
            c = fmaf(g4.y, c, g4.x * g4.z);
            float h = g4.w * ftanh_fast(c);
            if (step + 1 < TSTEPS) {       // each of 256 threads: one st.async
                uint32_t nb = (uint32_t)((step + 1) & 1);
                st_async_b32(rdst + nb * HBYTES + myoff, __float_as_uint(h),
                             rdst + BAROFF + nb * 8u);
            }
            if (t < 16) hs[step * HDIM + base + t] = h;
        }
    }
}

// ---------------- output: softmax(hs@W_act + b_act) ----------------
__global__ __launch_bounds__(256) void k_out(const float* __restrict__ hs,
                                             const float* __restrict__ W,
                                             const float* __restrict__ b,
                                             float* __restrict__ out) {
    __shared__ float hrow[8][HDIM];
    int warp = threadIdx.x >> 5, lane = threadIdx.x & 31;
    int row = blockIdx.x * 8 + warp;
    if (row >= TSTEPS) return;
    #pragma unroll
    for (int q = 0; q < 8; q++)
        hrow[warp][lane + q * 32] = hs[row * HDIM + lane + q * 32];
    __syncwarp();
    int c0 = lane, c1 = lane + 32;
    float acc0 = b[c0], acc1 = b[c1];
    #pragma unroll 8
    for (int k = 0; k < HDIM; k++) {
        float h = hrow[warp][k];
        acc0 = fmaf(h, __ldg(&W[k * ODIM + c0]), acc0);
        acc1 = fmaf(h, __ldg(&W[k * ODIM + c1]), acc1);
    }
    float m = fmaxf(acc0, acc1);
    #pragma unroll
    for (int s = 16; s > 0; s >>= 1) m = fmaxf(m, __shfl_xor_sync(0xffffffffu, m, s));
    float e0 = __expf(acc0 - m), e1 = __expf(acc1 - m);
    float s = e0 + e1;
    #pragma unroll
    for (int d = 16; d > 0; d >>= 1) s += __shfl_xor_sync(0xffffffffu, s, d);
    float inv = __fdividef(1.0f, s);
    out[row * ODIM + c0] = e0 * inv;
    out[row * ODIM + c1] = e1 * inv;
}

// ---------------- launch ----------------
extern "C" void kernel_launch(void* const* d_in, const int* in_sizes, int n_in,
                              void* d_out, int out_size) {
    const float* agent_state = (const float*)d_in[0];
    const float* goal_state  = (const float*)d_in[1];
    const int*   groups      = (const int*)  d_in[2];
    const float* W_goal      = (const float*)d_in[3];
    const float* b_goal      = (const float*)d_in[4];
    const float* W_g1        = (const float*)d_in[5];
    const float* b_g1        = (const float*)d_in[6];
    const float* W_g2        = (const float*)d_in[7];
    const float* b_g2        = (const float*)d_in[8];
    const float* W_ih        = (const float*)d_in[9];
    const float* W_hh        = (const float*)d_in[10];
    const float* b_lstm      = (const float*)d_in[11];
    const float* W_act       = (const float*)d_in[12];
    const float* b_act       = (const float*)d_in[13];
    float* out = (float*)d_out;

    float *X, *Y, *R, *ZS, *HS; int* RI;
    cudaGetSymbolAddress((void**)&X,  g_X);
    cudaGetSymbolAddress((void**)&Y,  g_Y);
    cudaGetSymbolAddress((void**)&R,  g_R);
    cudaGetSymbolAddress((void**)&ZS, g_zs);
    cudaGetSymbolAddress((void**)&HS, g_hs);
    cudaGetSymbolAddress((void**)&RI, g_rowidx);

    k_goal<<<1, 256>>>(goal_state, W_goal, b_goal, R);
    k_rowidx_init<<<NAGENTS / 256, 256>>>(RI);
    k_rowidx_scatter<<<NGROUPS * GSIZE / 256, 256>>>(groups, RI);

    k_group<1><<<NGROUPS, 256>>>(agent_state, groups, X);                 // U1
    k_gemm<<<dim3(4, 512), 256>>>(X, W_g1, b_g1, Y, NAGENTS, HDIM, HDIM, 1);   // H1
    k_group<0><<<NGROUPS, 256>>>(Y, nullptr, X);                          // U2
    k_gemm<<<dim3(4, 512), 256>>>(X, W_g2, b_g2, Y, NAGENTS, HDIM, HDIM, 1);   // H2
    k_pool<<<NGROUPS, 256>>>(Y, R);

    k_gemm<<<dim3(16, 17), 256>>>(R, W_ih, b_lstm, ZS, ZROWS, 1024, HDIM, 0);  // zs

    // 16-CTA cluster LSTM (nonportable cluster size)
    cudaFuncSetAttribute(k_lstm, cudaFuncAttributeNonPortableClusterSizeAllowed, 1);
    {
        cudaLaunchConfig_t cfg = {};
        cfg.gridDim  = dim3(16, 1, 1);
        cfg.blockDim = dim3(256, 1, 1);
        cfg.dynamicSmemBytes = 0;
        cfg.stream = 0;
        cudaLaunchAttribute at[1];
        at[0].id = cudaLaunchAttributeClusterDimension;
        at[0].val.clusterDim.x = 16;
        at[0].val.clusterDim.y = 1;
        at[0].val.clusterDim.z = 1;
        cfg.attrs = at;
        cfg.numAttrs = 1;
        cudaLaunchKernelEx(&cfg, k_lstm, (const float*)ZS, (const int*)RI, W_hh, (float*)HS);
    }

    k_out<<<(TSTEPS + 7) / 8, 256>>>(HS, W_act, b_act, out);
}

// round 17
// speedup vs baseline: 1.7735x; 1.0040x over previous
#include <cuda_runtime.h>
#include <cuda_bf16.h>
#include <cstdint>

#define NAGENTS 32768
#define HDIM    256
#define ODIM    64
#define NGROUPS 1024
#define GSIZE   32
#define TSTEPS  (NAGENTS + 1)
#define ZROWS   1026   /* 1024 pooled + goal + zero-feat row */

// ---------------- device scratch (allocation-free) ----------------
__device__ float g_X[NAGENTS * HDIM];
__device__ float g_Y[NAGENTS * HDIM];
__device__ float g_R[ZROWS * HDIM];          // rows: pooled[0..1023], goal_emb, zeros
__device__ float g_zs[ZROWS * 1024];         // distinct input projections (+bias)
__device__ float g_hs[TSTEPS * HDIM];        // all hidden states
__device__ int   g_rowidx[NAGENTS];

// ---------------- PTX helpers ----------------
__device__ __forceinline__ uint32_t smem_u32(const void* p) {
    return (uint32_t)__cvta_generic_to_shared(p);
}
__device__ __forceinline__ uint32_t mapa_u32(uint32_t addr, uint32_t rank) {
    uint32_t r;
    asm("mapa.shared::cluster.u32 %0, %1, %2;" : "=r"(r) : "r"(addr), "r"(rank));
    return r;
}
__device__ __forceinline__ void st_async_b32(uint32_t daddr, uint32_t val, uint32_t dbar) {
    asm volatile("st.async.shared::cluster.mbarrier::complete_tx::bytes.b32 [%0], %1, [%2];"
                 :: "r"(daddr), "r"(val), "r"(dbar) : "memory");
}
__device__ __forceinline__ void mbar_init(uint32_t addr, uint32_t cnt) {
    asm volatile("mbarrier.init.shared.b64 [%0], %1;" :: "r"(addr), "r"(cnt) : "memory");
}
__device__ __forceinline__ void mbar_arrive_expect_tx(uint32_t addr, uint32_t bytes) {
    asm volatile("mbarrier.arrive.expect_tx.shared.b64 _, [%0], %1;"
                 :: "r"(addr), "r"(bytes) : "memory");
}
// CTA-scope acquire wait: st.async commits remote data to OUR smem before
// complete_tx is counted; acquire.cta orders our subsequent ld.shared.
__device__ __forceinline__ void mbar_wait(uint32_t addr, uint32_t parity) {
    asm volatile(
        "{\n\t.reg .pred P;\n\t"
        "WL_%=:\n\t"
        "mbarrier.try_wait.parity.acquire.cta.shared::cta.b64 P, [%0], %1, 0x989680;\n\t"
        "@P bra.uni WD_%=;\n\t"
        "bra.uni WL_%=;\n\t"
        "WD_%=:\n\t}"
        :: "r"(addr), "r"(parity) : "memory");
}
__device__ __forceinline__ uint32_t ctarank() {
    uint32_t r; asm("mov.u32 %0, %%cluster_ctarank;" : "=r"(r)); return r;
}
// Fast gates via single-op MUFU.TANH (tanh.approx.f32, sm_75+).
__device__ __forceinline__ float ftanh_fast(float x) {
    float y;
    asm("tanh.approx.f32 %0, %1;" : "=f"(y) : "f"(x));
    return y;
}
// packed f32x2 FMA/ADD (SASS FFMA2/FADD2 — only reachable via PTX)
#define FFMA2(acc, a, b) \
    asm("fma.rn.f32x2 %0, %1, %2, %3;" : "=l"(acc) : "l"(a), "l"(b), "l"(acc))
#define FADD2(out, a, b) \
    asm("add.rn.f32x2 %0, %1, %2;" : "=l"(out) : "l"(a), "l"(b))
__device__ __forceinline__ unsigned long long pack_f32x2(float lo, float hi) {
    unsigned long long r;
    asm("mov.b64 %0, {%1, %2};" : "=l"(r) : "r"(__float_as_uint(lo)), "r"(__float_as_uint(hi)));
    return r;
}
__device__ __forceinline__ float2 unpack_f32x2(unsigned long long v) {
    uint32_t lo, hi;
    asm("mov.b64 {%0, %1}, %2;" : "=r"(lo), "=r"(hi) : "l"(v));
    return make_float2(__uint_as_float(lo), __uint_as_float(hi));
}

// ---------------- goal embedding ----------------
__global__ void k_goal(const float* __restrict__ goal, const float* __restrict__ W,
                       const float* __restrict__ b, float* __restrict__ R) {
    __shared__ float gs[HDIM];
    int j = threadIdx.x;
    gs[j] = goal[j];
    __syncthreads();
    float acc = 0.f;
    #pragma unroll 8
    for (int k = 0; k < HDIM; k++) acc = fmaf(gs[k], W[k * HDIM + j], acc);
    R[1024 * HDIM + j] = fmaxf(acc + b[j], 0.f);
    R[1025 * HDIM + j] = 0.f;
}

// ---------------- rowidx ----------------
__global__ void k_rowidx_init(int* __restrict__ ri) {
    int i = blockIdx.x * blockDim.x + threadIdx.x;
    if (i < NAGENTS) ri[i] = 1025;
}
__global__ void k_rowidx_scatter(const int* __restrict__ groups, int* __restrict__ ri) {
    int e = blockIdx.x * blockDim.x + threadIdx.x;
    if (e < NGROUPS * GSIZE) ri[groups[e]] = e >> 5;
}

// ---------------- group aggregate ----------------
template <int GATHER>
__global__ void k_group(const float* __restrict__ src, const int* __restrict__ groups,
                        float* __restrict__ U) {
    __shared__ float rows[GSIZE][HDIM];
    __shared__ int   idx[GSIZE];
    int g = blockIdx.x, t = threadIdx.x;
    if (GATHER) {
        if (t < GSIZE) idx[t] = groups[g * GSIZE + t];
        __syncthreads();
    }
    #pragma unroll 4
    for (int m = 0; m < GSIZE; m++) {
        int r = GATHER ? idx[m] : (g * GSIZE + m);
        rows[m][t] = src[r * HDIM + t];
    }
    __syncthreads();
    float s = 0.f;
    #pragma unroll
    for (int m = 0; m < GSIZE; m++) s += rows[m][t];
    const float inv = 1.0f / 33.0f;
    #pragma unroll 4
    for (int m = 0; m < GSIZE; m++)
        U[(g * GSIZE + m) * HDIM + t] = (rows[m][t] + s) * inv;
}

// ---------------- pool ----------------
__global__ void k_pool(const float* __restrict__ H2, float* __restrict__ R) {
    int g = blockIdx.x, t = threadIdx.x;
    float s = 0.f;
    #pragma unroll
    for (int m = 0; m < GSIZE; m++) s += H2[(g * GSIZE + m) * HDIM + t];
    R[g * HDIM + t] = s * (1.0f / 32.0f);
}

// ---------------- tiled SGEMM: C = act(A[M,K]@B[K,N] + bias) ----------------
__global__ __launch_bounds__(256) void k_gemm(
    const float* __restrict__ A, const float* __restrict__ B,
    const float* __restrict__ bias, float* __restrict__ C,
    int M, int N, int K, int doRelu)
{
    __shared__ float As[64][20];
    __shared__ float Bs[16][64];
    int t = threadIdx.x;
    int tx = t & 15, ty = t >> 4;
    int bm = blockIdx.y * 64, bn = blockIdx.x * 64;
    int row0 = ty * 4, col0 = tx * 4;
    float acc[4][4];
    #pragma unroll
    for (int i = 0; i < 4; i++)
        #pragma unroll
        for (int j = 0; j < 4; j++) acc[i][j] = 0.f;

    int am = t >> 2, ak4 = (t & 3) * 4;
    for (int kb = 0; kb < K; kb += 16) {
        float4 av = make_float4(0.f, 0.f, 0.f, 0.f);
        if (bm + am < M)
            av = *reinterpret_cast<const float4*>(&A[(size_t)(bm + am) * K + kb + ak4]);
        *reinterpret_cast<float4*>(&As[am][ak4]) = av;
        #pragma unroll
        for (int i = 0; i < 4; i++) {
            int e = t + i * 256;
            int k = e >> 6, n = e & 63;
            Bs[k][n] = B[(size_t)(kb + k) * N + bn + n];
        }
        __syncthreads();
        #pragma unroll
        for (int k = 0; k < 16; k++) {
            float a0 = As[row0 + 0][k], a1 = As[row0 + 1][k];
            float a2 = As[row0 + 2][k], a3 = As[row0 + 3][k];
            float4 bv = *reinterpret_cast<const float4*>(&Bs[k][col0]);
            acc[0][0] = fmaf(a0, bv.x, acc[0][0]); acc[0][1] = fmaf(a0, bv.y, acc[0][1]);
            acc[0][2] = fmaf(a0, bv.z, acc[0][2]); acc[0][3] = fmaf(a0, bv.w, acc[0][3]);
            acc[1][0] = fmaf(a1, bv.x, acc[1][0]); acc[1][1] = fmaf(a1, bv.y, acc[1][1]);
            acc[1][2] = fmaf(a1, bv.z, acc[1][2]); acc[1][3] = fmaf(a1, bv.w, acc[1][3]);
            acc[2][0] = fmaf(a2, bv.x, acc[2][0]); acc[2][1] = fmaf(a2, bv.y, acc[2][1]);
            acc[2][2] = fmaf(a2, bv.z, acc[2][2]); acc[2][3] = fmaf(a2, bv.w, acc[2][3]);
            acc[3][0] = fmaf(a3, bv.x, acc[3][0]); acc[3][1] = fmaf(a3, bv.y, acc[3][1]);
            acc[3][2] = fmaf(a3, bv.z, acc[3][2]); acc[3][3] = fmaf(a3, bv.w, acc[3][3]);
        }
        __syncthreads();
    }
    #pragma unroll
    for (int i = 0; i < 4; i++) {
        int r = bm + row0 + i;
        if (r >= M) break;
        #pragma unroll
        for (int j = 0; j < 4; j++) {
            float v = acc[i][j] + bias[bn + col0 + j];
            if (doRelu) v = fmaxf(v, 0.f);
            C[(size_t)r * N + bn + col0 + j] = v;
        }
    }
}

// ---------------- persistent 16-CTA-cluster LSTM (256 threads, 2-stage reduce) ----------
// CTA r owns hidden indices [r*16, r*16+16) and gate cols {g*256 + r*16 + j}.
// 256 threads: warp w (0..7) lane l -> local col lc = w*8+(l&7) (64 cols),
// k-slice l>>3 (4 slices x 64 k; each spans two padded 36-word blocks).
// Reduce = 2 shfl stages (lane bits 3,4). Reducers (l<8) pre-activate gates.
// Senders: all 256 threads, col hj=t&15 -> rank t>>4 (coalesced half-warp sends).
// R17: packed-add accumulator epilogue; barrier re-arm moved after matvec issue.
#define HPAD    36
#define HBUFW   (8 * HPAD)          /* 288 words */
#define HBYTES  (HBUFW * 4)         /* 1152 B    */
#define BAROFF  (2 * HBYTES)        /* 2304      */
#define PAOFF   (BAROFF + 16)       /* 2320      */
#define SMBYTES (PAOFF + 2 * 64 * 4)

__global__ __launch_bounds__(256, 1)
void k_lstm(const float* __restrict__ zs, const int* __restrict__ rowidx,
            const float* __restrict__ W_hh, float* __restrict__ hs)
{
    __shared__ __align__(16) unsigned char sm[SMBYTES];
    float* smf = reinterpret_cast<float*>(sm);

    const int t = threadIdx.x;
    const int l = t & 31;
    const int w = t >> 5;
    const int lc   = w * 8 + (l & 7);   // local gate-col 0..63
    const int ksl  = l >> 3;            // k-slice 0..3 (64 k each)
    const int gate = lc >> 4;
    const int j    = lc & 15;
    const uint32_t rank = ctarank();
    const int base = rank * 16;
    const int gcol = gate * 256 + base + j;
    const int k0   = ksl * 64;

    // resident packed W_hh slice: 32 f32x2 regs (64 k-values for this col)
    unsigned long long w2[32];
    #pragma unroll
    for (int q = 0; q < 32; q++)
        w2[q] = pack_f32x2(W_hh[(size_t)(k0 + 2 * q) * 1024 + gcol],
                           W_hh[(size_t)(k0 + 2 * q + 1) * 1024 + gcol]);

    // zero both h buffers (incl. padding)
    for (int i = t; i < 2 * HBUFW; i += 256) smf[i] = 0.f;

    const uint32_t smb = smem_u32(sm);
    if (t == 0) {
        mbar_init(smb + BAROFF, 1);
        mbar_init(smb + BAROFF + 8, 1);
        mbar_arrive_expect_tx(smb + BAROFF, 1024);      // 16 CTAs x 16 floats
        mbar_arrive_expect_tx(smb + BAROFF + 8, 1024);
        asm volatile("fence.mbarrier_init.release.cluster;" ::: "memory");
    }
    __syncthreads();
    asm volatile("barrier.cluster.arrive.aligned;" ::: "memory");
    asm volatile("barrier.cluster.wait.aligned;" ::: "memory");

    // fan-out: thread t owns col hj=t&15, sends to rank t>>4 (16 lanes of a
    // half-warp -> same rank, contiguous words -> coalesced 64B DSMEM writes)
    const int hj = t & 15;
    const uint32_t rdst = mapa_u32(smb, (uint32_t)(t >> 4));
    // padded word offset of my h value (global idx base+hj) inside any h buffer
    const uint32_t myoff = 4u * ((rank >> 1) * HPAD + (rank & 1) * 16 + (uint32_t)hj);

    // gate-activation select constants for the l<8 reducer threads:
    // gates i,f,o: sigmoid(x)=0.5*tanh(0.5x)+0.5 ; gate g: tanh(x)
    const bool isG   = (gate == 2);
    const float xscl = isG ? 1.0f : 0.5f;

    float c = 0.f;                 // cell state for col base+hj (replicated x16 threads)
    uint32_t ph0 = 0, ph1 = 0;

    for (int step = 0; step < TSTEPS; step++) {
        // l<8 reducer threads: prefetch this col's z value (hidden under the wait)
        float zv = 0.f;
        if (l < 8) {
            int row = (step == NAGENTS) ? 1024 : __ldg(&rowidx[step]);
            zv = __ldg(&zs[(size_t)row * 1024 + gcol]);
        }

        const int buf = step & 1;
        if (step > 0) {            // wait for h(step-1) fan-in (CTA-scope acquire)
            if (buf) { mbar_wait(smb + BAROFF + 8, ph1); ph1 ^= 1; }
            else     { mbar_wait(smb + BAROFF, ph0); ph0 ^= 1; }
        }

        // matvec: 64 k for (col, slice), split over the two padded 36-word blocks.
        // Bank audit per LDS.128: 4 slice bases 288B apart -> word ranges
        // {0,8,16,24}+[0..3] (first block) / {4,12,20,28}+[0..3] (second) — disjoint.
        const ulonglong2* hpA = reinterpret_cast<const ulonglong2*>(
            sm + buf * HBYTES + (2 * ksl) * (HPAD * 4));
        const ulonglong2* hpB = reinterpret_cast<const ulonglong2*>(
            sm + buf * HBYTES + (2 * ksl + 1) * (HPAD * 4));
        unsigned long long a0 = 0ull, a1 = 0ull, a2 = 0ull, a3 = 0ull;
        #pragma unroll
        for (int q = 0; q < 4; q++) {
            ulonglong2 ha = hpA[2 * q];
            ulonglong2 hb = hpA[2 * q + 1];
            FFMA2(a0, ha.x, w2[4 * q + 0]);
            FFMA2(a1, ha.y, w2[4 * q + 1]);
            FFMA2(a0, hb.x, w2[4 * q + 2]);
            FFMA2(a1, hb.y, w2[4 * q + 3]);
        }
        #pragma unroll
        for (int q = 0; q < 4; q++) {
            ulonglong2 ha = hpB[2 * q];
            ulonglong2 hb = hpB[2 * q + 1];
            FFMA2(a2, ha.x, w2[16 + 4 * q + 0]);
            FFMA2(a3, ha.y, w2[16 + 4 * q + 1]);
            FFMA2(a2, hb.x, w2[16 + 4 * q + 2]);
            FFMA2(a3, hb.y, w2[16 + 4 * q + 3]);
        }

        // re-arm the just-consumed barrier AFTER the matvec loads are issued:
        // off the wait->LDS critical edge; foreign txs for the next phase of this
        // barrier can't arrive for ~a full step (safe margin).
        if (step > 0 && t == 0)
            mbar_arrive_expect_tx(smb + BAROFF + (buf ? 8 : 0), 1024);

        // packed-add accumulator collapse: 3 FADD2 + 1 unpack + 1 FADD
        unsigned long long s01, s23;
        FADD2(s01, a0, a1);
        FADD2(s23, a2, a3);
        FADD2(s01, s01, s23);
        float2 fs = unpack_f32x2(s01);
        float v = fs.x + fs.y;
        // reduce across the 4 k-slices (lane bits 3,4) — 2 stages
        v += __shfl_xor_sync(0xffffffffu, v, 8);
        v += __shfl_xor_sync(0xffffffffu, v, 16);
        if (l < 8) {
            // pre-activate: one MUFU here, off the post-barrier critical path
            float x = v + zv;
            float y = ftanh_fast(x * xscl);
            float a = isG ? y : fmaf(0.5f, y, 0.5f);
            smf[(PAOFF >> 2) + buf * 64 + j * 4 + gate] = a;   // pa[buf][j][gate]
        }
        __syncthreads();                                        // one bar per step

        {
            float4 g4 = *reinterpret_cast<const float4*>(
                &smf[(PAOFF >> 2) + buf * 64 + hj * 4]);
            // g4 = (a_i, a_f, a_g, a_o), already activated
            c = fmaf(g4.y, c, g4.x * g4.z);
            float h = g4.w * ftanh_fast(c);
            if (step + 1 < TSTEPS) {       // each of 256 threads: one st.async
                uint32_t nb = (uint32_t)((step + 1) & 1);
                st_async_b32(rdst + nb * HBYTES + myoff, __float_as_uint(h),
                             rdst + BAROFF + nb * 8u);
            }
            if (t < 16) hs[step * HDIM + base + t] = h;
        }
    }
}

// ---------------- output: softmax(hs@W_act + b_act) ----------------
__global__ __launch_bounds__(256) void k_out(const float* __restrict__ hs,
                                             const float* __restrict__ W,
                                             const float* __restrict__ b,
                                             float* __restrict__ out) {
    __shared__ float hrow[8][HDIM];
    int warp = threadIdx.x >> 5, lane = threadIdx.x & 31;
    int row = blockIdx.x * 8 + warp;
    if (row >= TSTEPS) return;
    #pragma unroll
    for (int q = 0; q < 8; q++)
        hrow[warp][lane + q * 32] = hs[row * HDIM + lane + q * 32];
    __syncwarp();
    int c0 = lane, c1 = lane + 32;
    float acc0 = b[c0], acc1 = b[c1];
    #pragma unroll 8
    for (int k = 0; k < HDIM; k++) {
        float h = hrow[warp][k];
        acc0 = fmaf(h, __ldg(&W[k * ODIM + c0]), acc0);
        acc1 = fmaf(h, __ldg(&W[k * ODIM + c1]), acc1);
    }
    float m = fmaxf(acc0, acc1);
    #pragma unroll
    for (int s = 16; s > 0; s >>= 1) m = fmaxf(m, __shfl_xor_sync(0xffffffffu, m, s));
    float e0 = __expf(acc0 - m), e1 = __expf(acc1 - m);
    float s = e0 + e1;
    #pragma unroll
    for (int d = 16; d > 0; d >>= 1) s += __shfl_xor_sync(0xffffffffu, s, d);
    float inv = __fdividef(1.0f, s);
    out[row * ODIM + c0] = e0 * inv;
    out[row * ODIM + c1] = e1 * inv;
}

// ---------------- launch ----------------
extern "C" void kernel_launch(void* const* d_in, const int* in_sizes, int n_in,
                              void* d_out, int out_size) {
    const float* agent_state = (const float*)d_in[0];
    const float* goal_state  = (const float*)d_in[1];
    const int*   groups      = (const int*)  d_in[2];
    const float* W_goal      = (const float*)d_in[3];
    const float* b_goal      = (const float*)d_in[4];
    const float* W_g1        = (const float*)d_in[5];
    const float* b_g1        = (const float*)d_in[6];
    const float* W_g2        = (const float*)d_in[7];
    const float* b_g2        = (const float*)d_in[8];
    const float* W_ih        = (const float*)d_in[9];
    const float* W_hh        = (const float*)d_in[10];
    const float* b_lstm      = (const float*)d_in[11];
    const float* W_act       = (const float*)d_in[12];
    const float* b_act       = (const float*)d_in[13];
    float* out = (float*)d_out;

    float *X, *Y, *R, *ZS, *HS; int* RI;
    cudaGetSymbolAddress((void**)&X,  g_X);
    cudaGetSymbolAddress((void**)&Y,  g_Y);
    cudaGetSymbolAddress((void**)&R,  g_R);
    cudaGetSymbolAddress((void**)&ZS, g_zs);
    cudaGetSymbolAddress((void**)&HS, g_hs);
    cudaGetSymbolAddress((void**)&RI, g_rowidx);

    k_goal<<<1, 256>>>(goal_state, W_goal, b_goal, R);
    k_rowidx_init<<<NAGENTS / 256, 256>>>(RI);
    k_rowidx_scatter<<<NGROUPS * GSIZE / 256, 256>>>(groups, RI);

    k_group<1><<<NGROUPS, 256>>>(agent_state, groups, X);                 // U1
    k_gemm<<<dim3(4, 512), 256>>>(X, W_g1, b_g1, Y, NAGENTS, HDIM, HDIM, 1);   // H1
    k_group<0><<<NGROUPS, 256>>>(Y, nullptr, X);                          // U2
    k_gemm<<<dim3(4, 512), 256>>>(X, W_g2, b_g2, Y, NAGENTS, HDIM, HDIM, 1);   // H2
    k_pool<<<NGROUPS, 256>>>(Y, R);

    k_gemm<<<dim3(16, 17), 256>>>(R, W_ih, b_lstm, ZS, ZROWS, 1024, HDIM, 0);  // zs

    // 16-CTA cluster LSTM (nonportable cluster size)
    cudaFuncSetAttribute(k_lstm, cudaFuncAttributeNonPortableClusterSizeAllowed, 1);
    {
        cudaLaunchConfig_t cfg = {};
        cfg.gridDim  = dim3(16, 1, 1);
        cfg.blockDim = dim3(256, 1, 1);
        cfg.dynamicSmemBytes = 0;
        cfg.stream = 0;
        cudaLaunchAttribute at[1];
        at[0].id = cudaLaunchAttributeClusterDimension;
        at[0].val.clusterDim.x = 16;
        at[0].val.clusterDim.y = 1;
        at[0].val.clusterDim.z = 1;
        cfg.attrs = at;
        cfg.numAttrs = 1;
        cudaLaunchKernelEx(&cfg, k_lstm, (const float*)ZS, (const int*)RI, W_hh, (float*)HS);
    }

    k_out<<<(TSTEPS + 7) / 8, 256>>>(HS, W_act, b_act, out);
}